// round 2
// baseline (speedup 1.0000x reference)
#include <cuda_runtime.h>
#include <cuda_bf16.h>
#include <cstdint>

#define N_NODES 50000
#define N_ADJ   6
#define NNZ_C   800000
#define KH      256   // n_hid_prev
#define NH      128   // n_hid
#define LN_EPS  1e-5f

// ---------------- scratch (static device globals; no runtime alloc) ----------
__device__ float g_h [N_NODES * NH];   // states[0] = x@W + b
__device__ float g_s1[N_NODES * NH];   // states[1]
__device__ float g_s2[N_NODES * NH];   // states[2]
// states[3] accumulates directly into d_out, then LN+GELU in place.

// ---------------- GEMM: H = X[50000,256] @ W[256,128] + b --------------------
// tile 64(M) x 128(N), 256 threads, TK=16. Each thread: 8x4 micro-tile.
__global__ __launch_bounds__(256)
void gemm_kernel(const float* __restrict__ X, const float* __restrict__ W,
                 const float* __restrict__ bias, float* __restrict__ H) {
    __shared__ float As[16][65];    // [k][m], padded to dodge write conflicts
    __shared__ float Bs[16][128];   // [k][n]

    const int m0  = blockIdx.x * 64;
    const int tid = threadIdx.x;
    const int tcol = (tid & 31) * 4;   // 0..124
    const int trow = (tid >> 5) * 8;   // 0..56

    float acc[8][4];
#pragma unroll
    for (int r = 0; r < 8; r++)
#pragma unroll
        for (int c = 0; c < 4; c++) acc[r][c] = 0.f;

    const int ra = tid >> 2;           // 0..63
    const int kq = (tid & 3) * 4;      // 0,4,8,12

    for (int k0 = 0; k0 < KH; k0 += 16) {
        // A tile: 64 rows x 16 k, one float4 per thread, stored transposed
        int grow = m0 + ra;
        float4 av = make_float4(0.f, 0.f, 0.f, 0.f);
        if (grow < N_NODES)
            av = *(const float4*)(X + (size_t)grow * KH + k0 + kq);
        As[kq + 0][ra] = av.x; As[kq + 1][ra] = av.y;
        As[kq + 2][ra] = av.z; As[kq + 3][ra] = av.w;

        // B tile: 16 x 128 floats = 512 float4; 2 per thread
#pragma unroll
        for (int i = 0; i < 2; i++) {
            int idx = tid + i * 256;       // 0..511
            int kb  = idx >> 5;            // 0..15
            int nb  = (idx & 31) * 4;      // 0..124
            *(float4*)&Bs[kb][nb] = *(const float4*)(W + (size_t)(k0 + kb) * NH + nb);
        }
        __syncthreads();

#pragma unroll
        for (int k = 0; k < 16; k++) {
            float4 bv = *(const float4*)&Bs[k][tcol];
#pragma unroll
            for (int r = 0; r < 8; r++) {
                float a = As[k][trow + r];
                acc[r][0] += a * bv.x; acc[r][1] += a * bv.y;
                acc[r][2] += a * bv.z; acc[r][3] += a * bv.w;
            }
        }
        __syncthreads();
    }

    float4 bb = *(const float4*)(bias + tcol);
#pragma unroll
    for (int r = 0; r < 8; r++) {
        int grow = m0 + trow + r;
        if (grow < N_NODES) {
            float4 o = make_float4(acc[r][0] + bb.x, acc[r][1] + bb.y,
                                   acc[r][2] + bb.z, acc[r][3] + bb.w);
            *(float4*)(H + (size_t)grow * NH + tcol) = o;
        }
    }
}

// ---------------- zero fill ---------------------------------------------------
__global__ __launch_bounds__(256)
void zero_kernel(float* __restrict__ p, int n4) {
    float4 z = make_float4(0.f, 0.f, 0.f, 0.f);
    int stride = gridDim.x * blockDim.x;
    for (int j = blockIdx.x * blockDim.x + threadIdx.x; j < n4; j += stride)
        ((float4*)p)[j] = z;
}

// ---------------- SpMM: dst += A[idx_arr[idx_off]] @ src ----------------------
// One warp per nnz; 512B coalesced gather; 128-bit vector atomics for scatter.
__global__ __launch_bounds__(256)
void spmm_kernel(const int* __restrict__ rows_all, const int* __restrict__ cols_all,
                 const float* __restrict__ vals_all, const int* __restrict__ idx_arr,
                 int idx_off, const float* __restrict__ src, float* __restrict__ dst) {
    const int a = __ldg(idx_arr + idx_off);
    const int*   rows = rows_all + (size_t)a * NNZ_C;
    const int*   cols = cols_all + (size_t)a * NNZ_C;
    const float* vals = vals_all + (size_t)a * NNZ_C;

    const int lane = threadIdx.x & 31;
    const int warp = (blockIdx.x * blockDim.x + threadIdx.x) >> 5;
    const int nw   = (gridDim.x * blockDim.x) >> 5;

    for (int e = warp; e < NNZ_C; e += nw) {
        int   r = __ldg(rows + e);
        int   c = __ldg(cols + e);
        float v = __ldg(vals + e);
        float4 s = *(const float4*)(src + (size_t)c * NH + lane * 4);
        float* dp = dst + (size_t)r * NH + lane * 4;
        asm volatile("red.global.add.v4.f32 [%0], {%1,%2,%3,%4};"
                     :: "l"(dp), "f"(s.x * v), "f"(s.y * v), "f"(s.z * v), "f"(s.w * v)
                     : "memory");
    }
}

// ---------------- LayerNorm (dim=128) + exact-erf GELU, in place --------------
__global__ __launch_bounds__(128)
void ln_gelu_kernel(float* __restrict__ y, const float* __restrict__ gamma,
                    const float* __restrict__ beta) {
    const int row = blockIdx.x;
    const int t   = threadIdx.x;          // 128 threads
    float v = y[(size_t)row * NH + t];

    float s = v, s2 = v * v;
#pragma unroll
    for (int o = 16; o; o >>= 1) {
        s  += __shfl_xor_sync(0xffffffffu, s,  o);
        s2 += __shfl_xor_sync(0xffffffffu, s2, o);
    }
    __shared__ float sh[8];
    int w = t >> 5;
    if ((t & 31) == 0) { sh[w] = s; sh[4 + w] = s2; }
    __syncthreads();
    float ts  = sh[0] + sh[1] + sh[2] + sh[3];
    float ts2 = sh[4] + sh[5] + sh[6] + sh[7];

    float mu  = ts * (1.f / NH);
    float var = ts2 * (1.f / NH) - mu * mu;
    float inv = rsqrtf(var + LN_EPS);
    float yn  = (v - mu) * inv * __ldg(gamma + t) + __ldg(beta + t);
    float g   = 0.5f * yn * (1.f + erff(yn * 0.70710678118654752f));
    y[(size_t)row * NH + t] = g;
}

// -----------------------------------------------------------------------------
extern "C" void kernel_launch(void* const* d_in, const int* in_sizes, int n_in,
                              void* d_out, int out_size) {
    const float* x         = (const float*)d_in[0];   // [50000,256]
    const int*   adj_rows  = (const int*)  d_in[1];   // [6,800000]
    const int*   adj_cols  = (const int*)  d_in[2];   // [6,800000]
    const float* adj_vals  = (const float*)d_in[3];   // [6,800000]
    const int*   idxes_seq = (const int*)  d_in[4];   // [3]
    const int*   idxes_res = (const int*)  d_in[5];   // [3]
    const float* W         = (const float*)d_in[6];   // [256,128]
    const float* b         = (const float*)d_in[7];   // [128]
    const float* gamma     = (const float*)d_in[8];   // [128]
    const float* beta      = (const float*)d_in[9];   // [128]
    float* out = (float*)d_out;                       // [50000,128]

    float* h  = nullptr; float* s1 = nullptr; float* s2 = nullptr;
    cudaGetSymbolAddress((void**)&h,  g_h);
    cudaGetSymbolAddress((void**)&s1, g_s1);
    cudaGetSymbolAddress((void**)&s2, g_s2);

    const int gemm_blocks = (N_NODES + 63) / 64;
    const int n4 = N_NODES * NH / 4;
    const dim3 sgrid(1184), sblk(256);   // 1184 blocks = 8 waves on 148 SMs

    // states[0] = x @ W + b
    gemm_kernel<<<gemm_blocks, 256>>>(x, W, b, h);

    // step 0: s1 = A[seq0] @ h
    zero_kernel<<<1184, 256>>>(s1, n4);
    spmm_kernel<<<sgrid, sblk>>>(adj_rows, adj_cols, adj_vals, idxes_seq, 0, h, s1);

    // step 1: s2 = A[seq1] @ s1 + A[res0] @ h
    zero_kernel<<<1184, 256>>>(s2, n4);
    spmm_kernel<<<sgrid, sblk>>>(adj_rows, adj_cols, adj_vals, idxes_seq, 1, s1, s2);
    spmm_kernel<<<sgrid, sblk>>>(adj_rows, adj_cols, adj_vals, idxes_res, 0, h,  s2);

    // step 2: out = A[seq2] @ s2 + A[res1] @ h + A[res2] @ s1
    zero_kernel<<<1184, 256>>>(out, n4);
    spmm_kernel<<<sgrid, sblk>>>(adj_rows, adj_cols, adj_vals, idxes_seq, 2, s2, out);
    spmm_kernel<<<sgrid, sblk>>>(adj_rows, adj_cols, adj_vals, idxes_res, 1, h,  out);
    spmm_kernel<<<sgrid, sblk>>>(adj_rows, adj_cols, adj_vals, idxes_res, 2, s1, out);

    // LN + exact GELU in place on out
    ln_gelu_kernel<<<N_NODES, NH>>>(out, gamma, beta);
}

// round 3
// speedup vs baseline: 1.8417x; 1.8417x over previous
#include <cuda_runtime.h>
#include <cuda_bf16.h>
#include <cstdint>

#define N_NODES 50000
#define N_ADJ   6
#define NNZ_C   800000
#define KH      256   // n_hid_prev
#define NH      128   // n_hid
#define LN_EPS  1e-5f
#define NBLK    98    // ceil(50000/512) blocks per matrix for the scan

// ---------------- scratch (static device globals; no runtime alloc) ----------
__device__ float g_h [N_NODES * NH];            // states[0] = x@W + b
__device__ float g_s1[N_NODES * NH];            // states[1]
__device__ float g_s2[N_NODES * NH];            // states[2]
__device__ int   g_cnt[N_ADJ * N_NODES];        // per-row nnz histogram
__device__ int   g_cur[N_ADJ * N_NODES];        // scatter cursors
__device__ int   g_rowptr[N_ADJ * (N_NODES + 1)];
__device__ int   g_bsum[N_ADJ * NBLK];          // per-block scan partials
__device__ int2  g_ent[(size_t)N_ADJ * NNZ_C];  // packed (col, val) per edge, CSR order

// ---------------- GEMM: H = X[50000,256] @ W[256,128] + b --------------------
__global__ __launch_bounds__(256)
void gemm_kernel(const float* __restrict__ X, const float* __restrict__ W,
                 const float* __restrict__ bias, float* __restrict__ H) {
    __shared__ float As[16][65];
    __shared__ float Bs[16][128];

    const int m0  = blockIdx.x * 64;
    const int tid = threadIdx.x;
    const int tcol = (tid & 31) * 4;
    const int trow = (tid >> 5) * 8;

    float acc[8][4];
#pragma unroll
    for (int r = 0; r < 8; r++)
#pragma unroll
        for (int c = 0; c < 4; c++) acc[r][c] = 0.f;

    const int ra = tid >> 2;
    const int kq = (tid & 3) * 4;

    for (int k0 = 0; k0 < KH; k0 += 16) {
        int grow = m0 + ra;
        float4 av = make_float4(0.f, 0.f, 0.f, 0.f);
        if (grow < N_NODES)
            av = *(const float4*)(X + (size_t)grow * KH + k0 + kq);
        As[kq + 0][ra] = av.x; As[kq + 1][ra] = av.y;
        As[kq + 2][ra] = av.z; As[kq + 3][ra] = av.w;

#pragma unroll
        for (int i = 0; i < 2; i++) {
            int idx = tid + i * 256;
            int kb  = idx >> 5;
            int nb  = (idx & 31) * 4;
            *(float4*)&Bs[kb][nb] = *(const float4*)(W + (size_t)(k0 + kb) * NH + nb);
        }
        __syncthreads();

#pragma unroll
        for (int k = 0; k < 16; k++) {
            float4 bv = *(const float4*)&Bs[k][tcol];
#pragma unroll
            for (int r = 0; r < 8; r++) {
                float a = As[k][trow + r];
                acc[r][0] += a * bv.x; acc[r][1] += a * bv.y;
                acc[r][2] += a * bv.z; acc[r][3] += a * bv.w;
            }
        }
        __syncthreads();
    }

    float4 bb = *(const float4*)(bias + tcol);
#pragma unroll
    for (int r = 0; r < 8; r++) {
        int grow = m0 + trow + r;
        if (grow < N_NODES) {
            float4 o = make_float4(acc[r][0] + bb.x, acc[r][1] + bb.y,
                                   acc[r][2] + bb.z, acc[r][3] + bb.w);
            *(float4*)(H + (size_t)grow * NH + tcol) = o;
        }
    }
}

// ---------------- CSR build pipeline -----------------------------------------
__global__ __launch_bounds__(256)
void zero_cnt_kernel() {
    int stride = gridDim.x * blockDim.x;
    for (int i = blockIdx.x * blockDim.x + threadIdx.x; i < N_ADJ * N_NODES; i += stride)
        g_cnt[i] = 0;
}

__global__ __launch_bounds__(256)
void hist_kernel(const int* __restrict__ rows_all) {
    const int total = N_ADJ * NNZ_C;
    int stride = gridDim.x * blockDim.x;
    for (int e = blockIdx.x * blockDim.x + threadIdx.x; e < total; e += stride) {
        int m = e / NNZ_C;
        int r = __ldg(rows_all + e);
        atomicAdd(&g_cnt[m * N_NODES + r], 1);
    }
}

// per-512-block exclusive scan; block totals -> g_bsum
__global__ __launch_bounds__(512)
void scan1_kernel() {
    const int m   = blockIdx.x / NBLK;
    const int blk = blockIdx.x % NBLK;
    const int tid = threadIdx.x;
    const int i   = blk * 512 + tid;

    int v = (i < N_NODES) ? g_cnt[m * N_NODES + i] : 0;
    int x = v;
    const int lane = tid & 31;
#pragma unroll
    for (int o = 1; o < 32; o <<= 1) {
        int n = __shfl_up_sync(0xffffffffu, x, o);
        if (lane >= o) x += n;
    }
    __shared__ int ws[16];
    if (lane == 31) ws[tid >> 5] = x;
    __syncthreads();
    if (tid < 16) {
        int y = ws[tid];
#pragma unroll
        for (int o = 1; o < 16; o <<= 1) {
            int n = __shfl_up_sync(0x0000ffffu, y, o);
            if (tid >= o) y += n;
        }
        ws[tid] = y;
    }
    __syncthreads();
    int w = tid >> 5;
    int off = (w > 0) ? ws[w - 1] : 0;
    int incl = x + off;
    if (i < N_NODES)
        g_rowptr[m * (N_NODES + 1) + i] = incl - v;   // exclusive within block
    if (tid == 511)
        g_bsum[blockIdx.x] = incl;                    // block total
}

// scan block totals per matrix (sequential per matrix; tiny)
__global__ void scan2_kernel() {
    int m = threadIdx.x;
    if (m < N_ADJ) {
        int run = 0;
        for (int b = 0; b < NBLK; b++) {
            int t = g_bsum[m * NBLK + b];
            g_bsum[m * NBLK + b] = run;
            run += t;
        }
    }
}

// add block bases; init cursors; finalize rowptr[N]
__global__ __launch_bounds__(256)
void scan3_kernel() {
    int stride = gridDim.x * blockDim.x;
    for (int i = blockIdx.x * blockDim.x + threadIdx.x; i < N_ADJ * N_NODES; i += stride) {
        int m = i / N_NODES;
        int r = i - m * N_NODES;
        int val = g_rowptr[m * (N_NODES + 1) + r] + g_bsum[m * NBLK + (r >> 9)];
        g_rowptr[m * (N_NODES + 1) + r] = val;
        g_cur[i] = val;
        if (r == 0) g_rowptr[m * (N_NODES + 1) + N_NODES] = NNZ_C;
    }
}

__global__ __launch_bounds__(256)
void scatter_kernel(const int* __restrict__ rows_all, const int* __restrict__ cols_all,
                    const float* __restrict__ vals_all) {
    const int total = N_ADJ * NNZ_C;
    int stride = gridDim.x * blockDim.x;
    for (int e = blockIdx.x * blockDim.x + threadIdx.x; e < total; e += stride) {
        int m = e / NNZ_C;
        int r = __ldg(rows_all + e);
        int c = __ldg(cols_all + e);
        float v = __ldg(vals_all + e);
        int pos = atomicAdd(&g_cur[m * N_NODES + r], 1);
        g_ent[(size_t)m * NNZ_C + pos] = make_int2(c, __float_as_int(v));
    }
}

// ---------------- fused CSR SpMM: one warp per output row ---------------------
// dst[row] = sum_t  A[*ia_t] @ src_t [row], optional fused LayerNorm + GELU.
__device__ __forceinline__ void row_accum(int a, int row, int lane,
                                          const float* __restrict__ src, float4& acc) {
    const int2* ent = g_ent + (size_t)a * NNZ_C;
    int base = a * (N_NODES + 1);
    int s = __ldg(&g_rowptr[base + row]);
    int e = __ldg(&g_rowptr[base + row + 1]);
    for (int j = s; j < e; j++) {
        int2 cv = __ldg(&ent[j]);                  // broadcast: same addr all lanes
        float v = __int_as_float(cv.y);
        float4 sv = *(const float4*)(src + (size_t)cv.x * NH + lane * 4);
        acc.x += v * sv.x; acc.y += v * sv.y;
        acc.z += v * sv.z; acc.w += v * sv.w;
    }
}

__global__ __launch_bounds__(256)
void spmm_csr_kernel(int nmat,
                     const int* __restrict__ ia0, const float* __restrict__ src0,
                     const int* __restrict__ ia1, const float* __restrict__ src1,
                     const int* __restrict__ ia2, const float* __restrict__ src2,
                     float* __restrict__ dst, int do_ln,
                     const float* __restrict__ gamma, const float* __restrict__ beta) {
    const int row  = (blockIdx.x * blockDim.x + threadIdx.x) >> 5;
    if (row >= N_NODES) return;
    const int lane = threadIdx.x & 31;

    float4 acc = make_float4(0.f, 0.f, 0.f, 0.f);
    row_accum(__ldg(ia0), row, lane, src0, acc);
    if (nmat > 1) row_accum(__ldg(ia1), row, lane, src1, acc);
    if (nmat > 2) row_accum(__ldg(ia2), row, lane, src2, acc);

    if (do_ln) {
        float s  = acc.x + acc.y + acc.z + acc.w;
        float s2 = acc.x * acc.x + acc.y * acc.y + acc.z * acc.z + acc.w * acc.w;
#pragma unroll
        for (int o = 16; o; o >>= 1) {
            s  += __shfl_xor_sync(0xffffffffu, s,  o);
            s2 += __shfl_xor_sync(0xffffffffu, s2, o);
        }
        float mu  = s * (1.f / NH);
        float var = s2 * (1.f / NH) - mu * mu;
        float inv = rsqrtf(var + LN_EPS);
        float4 g4 = *(const float4*)(gamma + lane * 4);
        float4 b4 = *(const float4*)(beta  + lane * 4);
        float y0 = (acc.x - mu) * inv * g4.x + b4.x;
        float y1 = (acc.y - mu) * inv * g4.y + b4.y;
        float y2 = (acc.z - mu) * inv * g4.z + b4.z;
        float y3 = (acc.w - mu) * inv * g4.w + b4.w;
        const float k = 0.70710678118654752f;
        acc.x = 0.5f * y0 * (1.f + erff(y0 * k));
        acc.y = 0.5f * y1 * (1.f + erff(y1 * k));
        acc.z = 0.5f * y2 * (1.f + erff(y2 * k));
        acc.w = 0.5f * y3 * (1.f + erff(y3 * k));
    }
    *(float4*)(dst + (size_t)row * NH + lane * 4) = acc;
}

// -----------------------------------------------------------------------------
extern "C" void kernel_launch(void* const* d_in, const int* in_sizes, int n_in,
                              void* d_out, int out_size) {
    const float* x         = (const float*)d_in[0];   // [50000,256]
    const int*   adj_rows  = (const int*)  d_in[1];   // [6,800000]
    const int*   adj_cols  = (const int*)  d_in[2];   // [6,800000]
    const float* adj_vals  = (const float*)d_in[3];   // [6,800000]
    const int*   idxes_seq = (const int*)  d_in[4];   // [3]
    const int*   idxes_res = (const int*)  d_in[5];   // [3]
    const float* W         = (const float*)d_in[6];   // [256,128]
    const float* b         = (const float*)d_in[7];   // [128]
    const float* gamma     = (const float*)d_in[8];   // [128]
    const float* beta      = (const float*)d_in[9];   // [128]
    float* out = (float*)d_out;                       // [50000,128]

    float* h  = nullptr; float* s1 = nullptr; float* s2 = nullptr;
    cudaGetSymbolAddress((void**)&h,  g_h);
    cudaGetSymbolAddress((void**)&s1, g_s1);
    cudaGetSymbolAddress((void**)&s2, g_s2);

    // --- states[0] = x @ W + b (overlaps nothing; first in stream) ---
    gemm_kernel<<<(N_NODES + 63) / 64, 256>>>(x, W, b, h);

    // --- CSR build for all 6 adjacency matrices ---
    zero_cnt_kernel<<<296, 256>>>();
    hist_kernel<<<1184, 256>>>(adj_rows);
    scan1_kernel<<<N_ADJ * NBLK, 512>>>();
    scan2_kernel<<<1, 32>>>();
    scan3_kernel<<<296, 256>>>();
    scatter_kernel<<<1184, 256>>>(adj_rows, adj_cols, adj_vals);

    // --- graph-conv steps, fully fused per step (no zeros, no atomics) ---
    const int sgrid = (N_NODES * 32 + 255) / 256;   // one warp per row
    // step 0: s1 = A[seq0] @ h
    spmm_csr_kernel<<<sgrid, 256>>>(1, idxes_seq + 0, h,
                                    nullptr, nullptr, nullptr, nullptr,
                                    s1, 0, nullptr, nullptr);
    // step 1: s2 = A[seq1] @ s1 + A[res0] @ h
    spmm_csr_kernel<<<sgrid, 256>>>(2, idxes_seq + 1, s1,
                                    idxes_res + 0, h, nullptr, nullptr,
                                    s2, 0, nullptr, nullptr);
    // step 2: out = LN+GELU( A[seq2] @ s2 + A[res1] @ h + A[res2] @ s1 )
    spmm_csr_kernel<<<sgrid, 256>>>(3, idxes_seq + 2, s2,
                                    idxes_res + 1, h, idxes_res + 2, s1,
                                    out, 1, gamma, beta);
}

// round 4
// speedup vs baseline: 1.8622x; 1.0111x over previous
#include <cuda_runtime.h>
#include <cuda_fp16.h>
#include <cstdint>

#define N_NODES 50000
#define N_ADJ   6
#define NNZ_C   800000
#define KH      256   // n_hid_prev
#define NH      128   // n_hid
#define LN_EPS  1e-5f
#define NBLK    98    // ceil(50000/512) scan blocks per matrix

// ---------------- scratch (static device globals; no runtime alloc) ----------
__device__ __half g_h [N_NODES * NH];           // states[0] = x@W + b   (fp16)
__device__ __half g_s1[N_NODES * NH];           // states[1]             (fp16)
__device__ __half g_s2[N_NODES * NH];           // states[2]             (fp16)
__device__ int    g_cnt[N_ADJ * N_NODES];
__device__ int    g_cur[N_ADJ * N_NODES];
__device__ int    g_rowptr[N_ADJ * (N_NODES + 1)];
__device__ int    g_bsum[N_ADJ * NBLK];
__device__ int2   g_ent[(size_t)N_ADJ * NNZ_C]; // packed (col, fp32 val), CSR order

// ---------------- GEMM: H = X[50000,256] @ W[256,128] + b  -> fp16 ----------
// tile 128(M) x 128(N), 256 threads, 8x8 microtile, TK=16.
__global__ __launch_bounds__(256, 2)
void gemm_kernel(const float* __restrict__ X, const float* __restrict__ W,
                 const float* __restrict__ bias, __half* __restrict__ H) {
    __shared__ float As[16][132];   // [k][m] transposed, padded
    __shared__ float Bs[16][128];   // [k][n]

    const int m0  = blockIdx.x * 128;
    const int tid = threadIdx.x;
    const int tx  = tid & 15;       // col group: cols tx*8 .. +8
    const int ty  = tid >> 4;       // row group: rows ty*8 .. +8

    float acc[8][8];
#pragma unroll
    for (int r = 0; r < 8; r++)
#pragma unroll
        for (int c = 0; c < 8; c++) acc[r][c] = 0.f;

    for (int k0 = 0; k0 < KH; k0 += 16) {
        // A tile: 128 rows x 16 k = 512 float4, 2 per thread, store transposed
#pragma unroll
        for (int i = 0; i < 2; i++) {
            int idx = tid + i * 256;       // 0..511
            int row = idx >> 2;            // 0..127
            int kq  = (idx & 3) * 4;
            int grow = m0 + row;
            float4 av = make_float4(0.f, 0.f, 0.f, 0.f);
            if (grow < N_NODES)
                av = *(const float4*)(X + (size_t)grow * KH + k0 + kq);
            As[kq + 0][row] = av.x; As[kq + 1][row] = av.y;
            As[kq + 2][row] = av.z; As[kq + 3][row] = av.w;
        }
        // B tile: 16 x 128 = 512 float4, 2 per thread
#pragma unroll
        for (int i = 0; i < 2; i++) {
            int idx = tid + i * 256;
            int kb  = idx >> 5;
            int nb  = (idx & 31) * 4;
            *(float4*)&Bs[kb][nb] = *(const float4*)(W + (size_t)(k0 + kb) * NH + nb);
        }
        __syncthreads();

#pragma unroll
        for (int k = 0; k < 16; k++) {
            float4 a0 = *(const float4*)&As[k][ty * 8];
            float4 a1 = *(const float4*)&As[k][ty * 8 + 4];
            float4 b0 = *(const float4*)&Bs[k][tx * 8];
            float4 b1 = *(const float4*)&Bs[k][tx * 8 + 4];
            float av[8] = {a0.x, a0.y, a0.z, a0.w, a1.x, a1.y, a1.z, a1.w};
            float bv[8] = {b0.x, b0.y, b0.z, b0.w, b1.x, b1.y, b1.z, b1.w};
#pragma unroll
            for (int r = 0; r < 8; r++)
#pragma unroll
                for (int c = 0; c < 8; c++) acc[r][c] += av[r] * bv[c];
        }
        __syncthreads();
    }

    float4 bb0 = *(const float4*)(bias + tx * 8);
    float4 bb1 = *(const float4*)(bias + tx * 8 + 4);
    const float bbv[8] = {bb0.x, bb0.y, bb0.z, bb0.w, bb1.x, bb1.y, bb1.z, bb1.w};
#pragma unroll
    for (int r = 0; r < 8; r++) {
        int grow = m0 + ty * 8 + r;
        if (grow < N_NODES) {
            __half2 p[4];
#pragma unroll
            for (int c = 0; c < 4; c++)
                p[c] = __floats2half2_rn(acc[r][2 * c] + bbv[2 * c],
                                         acc[r][2 * c + 1] + bbv[2 * c + 1]);
            uint4 o;
            o.x = *(unsigned*)&p[0]; o.y = *(unsigned*)&p[1];
            o.z = *(unsigned*)&p[2]; o.w = *(unsigned*)&p[3];
            *(uint4*)(H + (size_t)grow * NH + tx * 8) = o;
        }
    }
}

// ---------------- CSR build pipeline -----------------------------------------
__global__ __launch_bounds__(256)
void zero_cnt_kernel() {
    int stride = gridDim.x * blockDim.x;
    for (int i = blockIdx.x * blockDim.x + threadIdx.x; i < N_ADJ * N_NODES; i += stride)
        g_cnt[i] = 0;
}

__global__ __launch_bounds__(256)
void hist_kernel(const int* __restrict__ rows_all) {
    const int total = N_ADJ * NNZ_C;
    int stride = gridDim.x * blockDim.x;
    for (int e = blockIdx.x * blockDim.x + threadIdx.x; e < total; e += stride) {
        int m = e / NNZ_C;
        int r = __ldg(rows_all + e);
        atomicAdd(&g_cnt[m * N_NODES + r], 1);
    }
}

// per-512-block exclusive scan; block totals -> g_bsum
__global__ __launch_bounds__(512)
void scan1_kernel() {
    const int m   = blockIdx.x / NBLK;
    const int blk = blockIdx.x % NBLK;
    const int tid = threadIdx.x;
    const int i   = blk * 512 + tid;

    int v = (i < N_NODES) ? g_cnt[m * N_NODES + i] : 0;
    int x = v;
    const int lane = tid & 31;
#pragma unroll
    for (int o = 1; o < 32; o <<= 1) {
        int n = __shfl_up_sync(0xffffffffu, x, o);
        if (lane >= o) x += n;
    }
    __shared__ int ws[16];
    if (lane == 31) ws[tid >> 5] = x;
    __syncthreads();
    if (tid < 16) {
        int y = ws[tid];
#pragma unroll
        for (int o = 1; o < 16; o <<= 1) {
            int n = __shfl_up_sync(0x0000ffffu, y, o);
            if (tid >= o) y += n;
        }
        ws[tid] = y;
    }
    __syncthreads();
    int w = tid >> 5;
    int off = (w > 0) ? ws[w - 1] : 0;
    int incl = x + off;
    if (i < N_NODES)
        g_rowptr[m * (N_NODES + 1) + i] = incl - v;   // exclusive within block
    if (tid == 511)
        g_bsum[blockIdx.x] = incl;                    // block total
}

// warp-parallel scan of block totals: one warp per matrix
__global__ void scan2_kernel() {
    const int m    = blockIdx.x;          // 0..5
    const int lane = threadIdx.x;         // 32
    int v[4]; int s = 0;
#pragma unroll
    for (int k = 0; k < 4; k++) {
        int i = lane * 4 + k;
        v[k] = (i < NBLK) ? g_bsum[m * NBLK + i] : 0;
        s += v[k];
    }
    int x = s;
#pragma unroll
    for (int o = 1; o < 32; o <<= 1) {
        int n = __shfl_up_sync(0xffffffffu, x, o);
        if (lane >= o) x += n;
    }
    int excl = x - s;
#pragma unroll
    for (int k = 0; k < 4; k++) {
        int i = lane * 4 + k;
        if (i < NBLK) g_bsum[m * NBLK + i] = excl;
        excl += v[k];
    }
}

// add block bases; init cursors; finalize rowptr[N]
__global__ __launch_bounds__(256)
void scan3_kernel() {
    int stride = gridDim.x * blockDim.x;
    for (int i = blockIdx.x * blockDim.x + threadIdx.x; i < N_ADJ * N_NODES; i += stride) {
        int m = i / N_NODES;
        int r = i - m * N_NODES;
        int val = g_rowptr[m * (N_NODES + 1) + r] + g_bsum[m * NBLK + (r >> 9)];
        g_rowptr[m * (N_NODES + 1) + r] = val;
        g_cur[i] = val;
        if (r == 0) g_rowptr[m * (N_NODES + 1) + N_NODES] = NNZ_C;
    }
}

__global__ __launch_bounds__(256)
void scatter_kernel(const int* __restrict__ rows_all, const int* __restrict__ cols_all,
                    const float* __restrict__ vals_all) {
    const int total = N_ADJ * NNZ_C;
    int stride = gridDim.x * blockDim.x;
    for (int e = blockIdx.x * blockDim.x + threadIdx.x; e < total; e += stride) {
        int m = e / NNZ_C;
        int r = __ldg(rows_all + e);
        int c = __ldg(cols_all + e);
        float v = __ldg(vals_all + e);
        int pos = atomicAdd(&g_cur[m * N_NODES + r], 1);
        g_ent[(size_t)m * NNZ_C + pos] = make_int2(c, __float_as_int(v));
    }
}

// ---------------- fused CSR SpMM (fp16 gather, fp32 accumulate) ---------------
__device__ __forceinline__ void row_accum(int a, int row, int lane,
                                          const __half* __restrict__ src, float4& acc) {
    const int2* ent = g_ent + (size_t)a * NNZ_C;
    int base = a * (N_NODES + 1);
    int s = __ldg(&g_rowptr[base + row]);
    int e = __ldg(&g_rowptr[base + row + 1]);
#pragma unroll 2
    for (int j = s; j < e; j++) {
        int2 cv = __ldg(&ent[j]);                  // broadcast across warp
        float v = __int_as_float(cv.y);
        uint2 raw = __ldg((const uint2*)(src + (size_t)cv.x * NH) + lane);
        float2 f0 = __half22float2(*(__half2*)&raw.x);
        float2 f1 = __half22float2(*(__half2*)&raw.y);
        acc.x += v * f0.x; acc.y += v * f0.y;
        acc.z += v * f1.x; acc.w += v * f1.y;
    }
}

// steps 0/1: dst (fp16) = sum of 1..2 SpMMs
__global__ __launch_bounds__(256)
void spmm_h_kernel(int nmat,
                   const int* __restrict__ ia0, const __half* __restrict__ src0,
                   const int* __restrict__ ia1, const __half* __restrict__ src1,
                   __half* __restrict__ dst) {
    const int row  = (blockIdx.x * blockDim.x + threadIdx.x) >> 5;
    if (row >= N_NODES) return;
    const int lane = threadIdx.x & 31;

    float4 acc = make_float4(0.f, 0.f, 0.f, 0.f);
    row_accum(__ldg(ia0), row, lane, src0, acc);
    if (nmat > 1) row_accum(__ldg(ia1), row, lane, src1, acc);

    __half2 p0 = __floats2half2_rn(acc.x, acc.y);
    __half2 p1 = __floats2half2_rn(acc.z, acc.w);
    uint2 o; o.x = *(unsigned*)&p0; o.y = *(unsigned*)&p1;
    *((uint2*)(dst + (size_t)row * NH) + lane) = o;
}

// step 2: out (fp32) = LN+GELU( sum of 3 SpMMs )
__global__ __launch_bounds__(256)
void spmm_ln_kernel(const int* __restrict__ ia0, const __half* __restrict__ src0,
                    const int* __restrict__ ia1, const __half* __restrict__ src1,
                    const int* __restrict__ ia2, const __half* __restrict__ src2,
                    float* __restrict__ dst,
                    const float* __restrict__ gamma, const float* __restrict__ beta) {
    const int row  = (blockIdx.x * blockDim.x + threadIdx.x) >> 5;
    if (row >= N_NODES) return;
    const int lane = threadIdx.x & 31;

    float4 acc = make_float4(0.f, 0.f, 0.f, 0.f);
    row_accum(__ldg(ia0), row, lane, src0, acc);
    row_accum(__ldg(ia1), row, lane, src1, acc);
    row_accum(__ldg(ia2), row, lane, src2, acc);

    float s  = acc.x + acc.y + acc.z + acc.w;
    float s2 = acc.x * acc.x + acc.y * acc.y + acc.z * acc.z + acc.w * acc.w;
#pragma unroll
    for (int o = 16; o; o >>= 1) {
        s  += __shfl_xor_sync(0xffffffffu, s,  o);
        s2 += __shfl_xor_sync(0xffffffffu, s2, o);
    }
    float mu  = s * (1.f / NH);
    float var = s2 * (1.f / NH) - mu * mu;
    float inv = rsqrtf(var + LN_EPS);
    float4 g4 = *(const float4*)(gamma + lane * 4);
    float4 b4 = *(const float4*)(beta  + lane * 4);
    float y0 = (acc.x - mu) * inv * g4.x + b4.x;
    float y1 = (acc.y - mu) * inv * g4.y + b4.y;
    float y2 = (acc.z - mu) * inv * g4.z + b4.z;
    float y3 = (acc.w - mu) * inv * g4.w + b4.w;
    const float kk = 0.70710678118654752f;
    acc.x = 0.5f * y0 * (1.f + erff(y0 * kk));
    acc.y = 0.5f * y1 * (1.f + erff(y1 * kk));
    acc.z = 0.5f * y2 * (1.f + erff(y2 * kk));
    acc.w = 0.5f * y3 * (1.f + erff(y3 * kk));
    *(float4*)(dst + (size_t)row * NH + lane * 4) = acc;
}

// -----------------------------------------------------------------------------
extern "C" void kernel_launch(void* const* d_in, const int* in_sizes, int n_in,
                              void* d_out, int out_size) {
    const float* x         = (const float*)d_in[0];   // [50000,256]
    const int*   adj_rows  = (const int*)  d_in[1];   // [6,800000]
    const int*   adj_cols  = (const int*)  d_in[2];   // [6,800000]
    const float* adj_vals  = (const float*)d_in[3];   // [6,800000]
    const int*   idxes_seq = (const int*)  d_in[4];   // [3]
    const int*   idxes_res = (const int*)  d_in[5];   // [3]
    const float* W         = (const float*)d_in[6];   // [256,128]
    const float* b         = (const float*)d_in[7];   // [128]
    const float* gamma     = (const float*)d_in[8];   // [128]
    const float* beta      = (const float*)d_in[9];   // [128]
    float* out = (float*)d_out;                       // [50000,128]

    __half* h = nullptr; __half* s1 = nullptr; __half* s2 = nullptr;
    cudaGetSymbolAddress((void**)&h,  g_h);
    cudaGetSymbolAddress((void**)&s1, g_s1);
    cudaGetSymbolAddress((void**)&s2, g_s2);

    // --- states[0] = x @ W + b ---
    gemm_kernel<<<(N_NODES + 127) / 128, 256>>>(x, W, b, h);

    // --- CSR build for all 6 adjacency matrices ---
    zero_cnt_kernel<<<296, 256>>>();
    hist_kernel<<<1184, 256>>>(adj_rows);
    scan1_kernel<<<N_ADJ * NBLK, 512>>>();
    scan2_kernel<<<N_ADJ, 32>>>();
    scan3_kernel<<<296, 256>>>();
    scatter_kernel<<<1184, 256>>>(adj_rows, adj_cols, adj_vals);

    // --- graph-conv steps, fused, no atomics ---
    const int sgrid = (N_NODES * 32 + 255) / 256;   // one warp per row
    // step 0: s1 = A[seq0] @ h
    spmm_h_kernel<<<sgrid, 256>>>(1, idxes_seq + 0, h, nullptr, nullptr, s1);
    // step 1: s2 = A[seq1] @ s1 + A[res0] @ h
    spmm_h_kernel<<<sgrid, 256>>>(2, idxes_seq + 1, s1, idxes_res + 0, h, s2);
    // step 2: out = LN+GELU( A[seq2] @ s2 + A[res1] @ h + A[res2] @ s1 )
    spmm_ln_kernel<<<sgrid, 256>>>(idxes_seq + 2, s2, idxes_res + 1, h,
                                   idxes_res + 2, s1, out, gamma, beta);
}

// round 5
// speedup vs baseline: 2.5928x; 1.3923x over previous
#include <cuda_runtime.h>
#include <cuda_fp16.h>
#include <cstdint>

#define N_NODES 50000
#define N_ADJ   6
#define NNZ_C   800000
#define KH      256   // n_hid_prev
#define NH      128   // n_hid
#define LN_EPS  1e-5f
#define NBLK    98    // ceil(50000/512) scan blocks per matrix

#define GEMM_BLOCKS ((N_NODES + 127) / 128)   // 391
#define RANK_BLOCKS 1184

// ---------------- scratch (static device globals; no runtime alloc) ----------
__device__ __half g_h [N_NODES * NH];           // states[0] (fp16)
__device__ __half g_s1[N_NODES * NH];           // states[1] (fp16)
__device__ __half g_s2[N_NODES * NH];           // states[2] (fp16)
__device__ int    g_cnt[N_ADJ * N_NODES];       // per-row counts (atomic ranks)
__device__ int    g_rowptr[N_ADJ * (N_NODES + 1)];
__device__ int    g_bsum[N_ADJ * NBLK];
__device__ int    g_rank[(size_t)N_ADJ * NNZ_C];   // per-edge within-row rank
__device__ int2   g_ent[(size_t)N_ADJ * NNZ_C];    // (col, fp32 val), CSR order

// =============================================================================
// Fused kernel: blocks [0, GEMM_BLOCKS) do HMMA GEMM; the rest do the rank pass.
// =============================================================================
__device__ __forceinline__ uint32_t smem_u32(const void* p) {
    return (uint32_t)__cvta_generic_to_shared(p);
}

__global__ __launch_bounds__(256)
void fused_gemm_rank_kernel(const float* __restrict__ X, const float* __restrict__ W,
                            const float* __restrict__ bias, __half* __restrict__ H,
                            const int* __restrict__ rows_all) {
    if (blockIdx.x >= GEMM_BLOCKS) {
        // ---------------- rank pass: cnt[m][r]++ returning rank -------------
        const int total = N_ADJ * NNZ_C;
        int stride = RANK_BLOCKS * blockDim.x;
        for (int e = (blockIdx.x - GEMM_BLOCKS) * blockDim.x + threadIdx.x;
             e < total; e += stride) {
            int m = e / NNZ_C;
            int r = __ldg(rows_all + e);
            g_rank[e] = atomicAdd(&g_cnt[m * N_NODES + r], 1);
        }
        return;
    }

    // ---------------- GEMM: H = X[50000,256] @ W[256,128] + b  (fp16 HMMA) ---
    __shared__ __half As[128][40];   // [m][k], pad->conflict-free ldmatrix
    __shared__ __half Bs[32][136];   // [k][n], pad 8

    const int m0   = blockIdx.x * 128;
    const int tid  = threadIdx.x;
    const int wid  = tid >> 5;
    const int lane = tid & 31;
    const int wm   = wid >> 1;          // 0..3 -> rows wm*32
    const int wn   = wid & 1;           // 0..1 -> cols wn*64
    const int grp  = lane >> 3;

    float acc[2][8][4];
#pragma unroll
    for (int a = 0; a < 2; a++)
#pragma unroll
        for (int b = 0; b < 8; b++)
#pragma unroll
            for (int c = 0; c < 4; c++) acc[a][b][c] = 0.f;

    for (int k0 = 0; k0 < KH; k0 += 32) {
        // stage A: 128 rows x 32 k fp32 -> fp16. 1024 float4, 4/thread.
#pragma unroll
        for (int i = 0; i < 4; i++) {
            int idx = tid + i * 256;
            int row = idx >> 3;
            int kq  = (idx & 7) * 4;
            float4 v = make_float4(0.f, 0.f, 0.f, 0.f);
            if (m0 + row < N_NODES)
                v = *(const float4*)(X + (size_t)(m0 + row) * KH + k0 + kq);
            __half2 h0 = __floats2half2_rn(v.x, v.y);
            __half2 h1 = __floats2half2_rn(v.z, v.w);
            *(__half2*)&As[row][kq]     = h0;
            *(__half2*)&As[row][kq + 2] = h1;
        }
        // stage B: 32 k x 128 n fp32 -> fp16. 1024 float4, 4/thread.
#pragma unroll
        for (int i = 0; i < 4; i++) {
            int idx = tid + i * 256;
            int kk  = idx >> 5;
            int nq  = (idx & 31) * 4;
            float4 v = *(const float4*)(W + (size_t)(k0 + kk) * NH + nq);
            *(__half2*)&Bs[kk][nq]     = __floats2half2_rn(v.x, v.y);
            *(__half2*)&Bs[kk][nq + 2] = __floats2half2_rn(v.z, v.w);
        }
        __syncthreads();

#pragma unroll
        for (int ks = 0; ks < 32; ks += 16) {
            // A fragments for 2 m16 tiles (ldmatrix x4)
            uint32_t afr[2][4];
#pragma unroll
            for (int mt = 0; mt < 2; mt++) {
                int arow = wm * 32 + mt * 16 + (lane & 7) + ((grp & 1) << 3);
                int acol = ks + ((grp >> 1) << 3);
                uint32_t addr = smem_u32(&As[arow][acol]);
                asm volatile("ldmatrix.sync.aligned.m8n8.x4.shared.b16 {%0,%1,%2,%3}, [%4];"
                             : "=r"(afr[mt][0]), "=r"(afr[mt][1]),
                               "=r"(afr[mt][2]), "=r"(afr[mt][3]) : "r"(addr));
            }
            // B fragments: 4 ldmatrix.x4.trans cover 8 n8 tiles
            uint32_t bfr[8][2];
#pragma unroll
            for (int p = 0; p < 4; p++) {         // n-tile pairs (2p, 2p+1)
                int brow = ks + ((grp & 1) << 3) + (lane & 7);
                int bcol = wn * 64 + p * 16 + ((grp >> 1) << 3);
                uint32_t addr = smem_u32(&Bs[brow][bcol]);
                asm volatile("ldmatrix.sync.aligned.m8n8.x4.trans.shared.b16 {%0,%1,%2,%3}, [%4];"
                             : "=r"(bfr[2 * p][0]), "=r"(bfr[2 * p][1]),
                               "=r"(bfr[2 * p + 1][0]), "=r"(bfr[2 * p + 1][1]) : "r"(addr));
            }
#pragma unroll
            for (int mt = 0; mt < 2; mt++)
#pragma unroll
                for (int nt = 0; nt < 8; nt++) {
                    asm volatile(
                        "mma.sync.aligned.m16n8k16.row.col.f32.f16.f16.f32 "
                        "{%0,%1,%2,%3}, {%4,%5,%6,%7}, {%8,%9}, {%0,%1,%2,%3};"
                        : "+f"(acc[mt][nt][0]), "+f"(acc[mt][nt][1]),
                          "+f"(acc[mt][nt][2]), "+f"(acc[mt][nt][3])
                        : "r"(afr[mt][0]), "r"(afr[mt][1]),
                          "r"(afr[mt][2]), "r"(afr[mt][3]),
                          "r"(bfr[nt][0]), "r"(bfr[nt][1]));
                }
        }
        __syncthreads();
    }

    // epilogue: + bias, -> fp16
#pragma unroll
    for (int mt = 0; mt < 2; mt++) {
        int row0 = m0 + wm * 32 + mt * 16 + (lane >> 2);
#pragma unroll
        for (int nt = 0; nt < 8; nt++) {
            int col = wn * 64 + nt * 8 + (lane & 3) * 2;
            float b0 = __ldg(bias + col), b1 = __ldg(bias + col + 1);
            if (row0 < N_NODES) {
                __half2 o = __floats2half2_rn(acc[mt][nt][0] + b0, acc[mt][nt][1] + b1);
                *(__half2*)(H + (size_t)row0 * NH + col) = o;
            }
            if (row0 + 8 < N_NODES) {
                __half2 o = __floats2half2_rn(acc[mt][nt][2] + b0, acc[mt][nt][3] + b1);
                *(__half2*)(H + (size_t)(row0 + 8) * NH + col) = o;
            }
        }
    }
}

// ---------------- CSR build: zero, scans, place -------------------------------
__global__ __launch_bounds__(256)
void zero_cnt_kernel() {
    int stride = gridDim.x * blockDim.x;
    for (int i = blockIdx.x * blockDim.x + threadIdx.x; i < N_ADJ * N_NODES; i += stride)
        g_cnt[i] = 0;
}

__global__ __launch_bounds__(512)
void scan1_kernel() {
    const int m   = blockIdx.x / NBLK;
    const int blk = blockIdx.x % NBLK;
    const int tid = threadIdx.x;
    const int i   = blk * 512 + tid;

    int v = (i < N_NODES) ? g_cnt[m * N_NODES + i] : 0;
    int x = v;
    const int lane = tid & 31;
#pragma unroll
    for (int o = 1; o < 32; o <<= 1) {
        int n = __shfl_up_sync(0xffffffffu, x, o);
        if (lane >= o) x += n;
    }
    __shared__ int ws[16];
    if (lane == 31) ws[tid >> 5] = x;
    __syncthreads();
    if (tid < 16) {
        int y = ws[tid];
#pragma unroll
        for (int o = 1; o < 16; o <<= 1) {
            int n = __shfl_up_sync(0x0000ffffu, y, o);
            if (tid >= o) y += n;
        }
        ws[tid] = y;
    }
    __syncthreads();
    int w = tid >> 5;
    int off = (w > 0) ? ws[w - 1] : 0;
    int incl = x + off;
    if (i < N_NODES)
        g_rowptr[m * (N_NODES + 1) + i] = incl - v;
    if (tid == 511)
        g_bsum[blockIdx.x] = incl;
}

__global__ void scan2_kernel() {
    const int m    = blockIdx.x;
    const int lane = threadIdx.x;
    int v[4]; int s = 0;
#pragma unroll
    for (int k = 0; k < 4; k++) {
        int i = lane * 4 + k;
        v[k] = (i < NBLK) ? g_bsum[m * NBLK + i] : 0;
        s += v[k];
    }
    int x = s;
#pragma unroll
    for (int o = 1; o < 32; o <<= 1) {
        int n = __shfl_up_sync(0xffffffffu, x, o);
        if (lane >= o) x += n;
    }
    int excl = x - s;
#pragma unroll
    for (int k = 0; k < 4; k++) {
        int i = lane * 4 + k;
        if (i < NBLK) g_bsum[m * NBLK + i] = excl;
        excl += v[k];
    }
}

__global__ __launch_bounds__(256)
void scan3_kernel() {
    int stride = gridDim.x * blockDim.x;
    for (int i = blockIdx.x * blockDim.x + threadIdx.x; i < N_ADJ * N_NODES; i += stride) {
        int m = i / N_NODES;
        int r = i - m * N_NODES;
        g_rowptr[m * (N_NODES + 1) + r] += g_bsum[m * NBLK + (r >> 9)];
        if (r == 0) g_rowptr[m * (N_NODES + 1) + N_NODES] = NNZ_C;
    }
}

__global__ __launch_bounds__(256)
void place_kernel(const int* __restrict__ rows_all, const int* __restrict__ cols_all,
                  const float* __restrict__ vals_all) {
    const int total = N_ADJ * NNZ_C;
    int stride = gridDim.x * blockDim.x;
    for (int e = blockIdx.x * blockDim.x + threadIdx.x; e < total; e += stride) {
        int m = e / NNZ_C;
        int r = __ldg(rows_all + e);
        int c = __ldg(cols_all + e);
        float v = __ldg(vals_all + e);
        int pos = __ldg(&g_rowptr[m * (N_NODES + 1) + r]) + g_rank[e];
        g_ent[(size_t)m * NNZ_C + pos] = make_int2(c, __float_as_int(v));
    }
}

// ---------------- SpMM: 16 lanes per row, 4-deep entry prefetch ---------------
__device__ __forceinline__ void fma8(float* acc, float v, uint4 raw) {
    const __half2* h = (const __half2*)&raw;
#pragma unroll
    for (int q = 0; q < 4; q++) {
        float2 f = __half22float2(h[q]);
        acc[2 * q]     += v * f.x;
        acc[2 * q + 1] += v * f.y;
    }
}

__device__ __forceinline__ void row_accum16(int a, int row, int lane16,
                                            const __half* __restrict__ src, float* acc) {
    const int2* ent = g_ent + (size_t)a * NNZ_C;
    const int base = a * (N_NODES + 1);
    int s = __ldg(&g_rowptr[base + row]);
    int e = __ldg(&g_rowptr[base + row + 1]);
    int j = s;
    for (; j + 4 <= e; j += 4) {
        int2 c0 = __ldg(ent + j);
        int2 c1 = __ldg(ent + j + 1);
        int2 c2 = __ldg(ent + j + 2);
        int2 c3 = __ldg(ent + j + 3);
        uint4 r0 = __ldg((const uint4*)(src + (size_t)c0.x * NH) + lane16);
        uint4 r1 = __ldg((const uint4*)(src + (size_t)c1.x * NH) + lane16);
        uint4 r2 = __ldg((const uint4*)(src + (size_t)c2.x * NH) + lane16);
        uint4 r3 = __ldg((const uint4*)(src + (size_t)c3.x * NH) + lane16);
        fma8(acc, __int_as_float(c0.y), r0);
        fma8(acc, __int_as_float(c1.y), r1);
        fma8(acc, __int_as_float(c2.y), r2);
        fma8(acc, __int_as_float(c3.y), r3);
    }
    for (; j < e; j++) {
        int2 cv = __ldg(ent + j);
        uint4 rv = __ldg((const uint4*)(src + (size_t)cv.x * NH) + lane16);
        fma8(acc, __int_as_float(cv.y), rv);
    }
}

// steps 0/1: dst (fp16) = sum of 1..2 SpMMs
__global__ __launch_bounds__(256)
void spmm_h_kernel(int nmat,
                   const int* __restrict__ ia0, const __half* __restrict__ src0,
                   const int* __restrict__ ia1, const __half* __restrict__ src1,
                   __half* __restrict__ dst) {
    const int row = (blockIdx.x * blockDim.x + threadIdx.x) >> 4;
    if (row >= N_NODES) return;
    const int lane16 = threadIdx.x & 15;

    float acc[8];
#pragma unroll
    for (int q = 0; q < 8; q++) acc[q] = 0.f;
    row_accum16(__ldg(ia0), row, lane16, src0, acc);
    if (nmat > 1) row_accum16(__ldg(ia1), row, lane16, src1, acc);

    __half2 p[4];
#pragma unroll
    for (int q = 0; q < 4; q++) p[q] = __floats2half2_rn(acc[2 * q], acc[2 * q + 1]);
    uint4 o;
    o.x = *(unsigned*)&p[0]; o.y = *(unsigned*)&p[1];
    o.z = *(unsigned*)&p[2]; o.w = *(unsigned*)&p[3];
    *((uint4*)(dst + (size_t)row * NH) + lane16) = o;
}

// step 2: out (fp32) = LN+GELU( sum of 3 SpMMs )
__global__ __launch_bounds__(256)
void spmm_ln_kernel(const int* __restrict__ ia0, const __half* __restrict__ src0,
                    const int* __restrict__ ia1, const __half* __restrict__ src1,
                    const int* __restrict__ ia2, const __half* __restrict__ src2,
                    float* __restrict__ dst,
                    const float* __restrict__ gamma, const float* __restrict__ beta) {
    const int row = (blockIdx.x * blockDim.x + threadIdx.x) >> 4;
    if (row >= N_NODES) return;
    const int lane16 = threadIdx.x & 15;

    float acc[8];
#pragma unroll
    for (int q = 0; q < 8; q++) acc[q] = 0.f;
    row_accum16(__ldg(ia0), row, lane16, src0, acc);
    row_accum16(__ldg(ia1), row, lane16, src1, acc);
    row_accum16(__ldg(ia2), row, lane16, src2, acc);

    float s = 0.f, s2 = 0.f;
#pragma unroll
    for (int q = 0; q < 8; q++) { s += acc[q]; s2 += acc[q] * acc[q]; }
#pragma unroll
    for (int o = 8; o; o >>= 1) {
        s  += __shfl_xor_sync(0xffffffffu, s,  o, 16);
        s2 += __shfl_xor_sync(0xffffffffu, s2, o, 16);
    }
    float mu  = s * (1.f / NH);
    float var = s2 * (1.f / NH) - mu * mu;
    float inv = rsqrtf(var + LN_EPS);

    float4 g0 = *(const float4*)(gamma + lane16 * 8);
    float4 g1 = *(const float4*)(gamma + lane16 * 8 + 4);
    float4 b0 = *(const float4*)(beta  + lane16 * 8);
    float4 b1 = *(const float4*)(beta  + lane16 * 8 + 4);
    const float gv[8] = {g0.x, g0.y, g0.z, g0.w, g1.x, g1.y, g1.z, g1.w};
    const float bv[8] = {b0.x, b0.y, b0.z, b0.w, b1.x, b1.y, b1.z, b1.w};

    const float kk = 0.70710678118654752f;
    float o8[8];
#pragma unroll
    for (int q = 0; q < 8; q++) {
        float y = (acc[q] - mu) * inv * gv[q] + bv[q];
        o8[q] = 0.5f * y * (1.f + erff(y * kk));
    }
    float* dp = dst + (size_t)row * NH + lane16 * 8;
    *(float4*)dp       = make_float4(o8[0], o8[1], o8[2], o8[3]);
    *(float4*)(dp + 4) = make_float4(o8[4], o8[5], o8[6], o8[7]);
}

// -----------------------------------------------------------------------------
extern "C" void kernel_launch(void* const* d_in, const int* in_sizes, int n_in,
                              void* d_out, int out_size) {
    const float* x         = (const float*)d_in[0];
    const int*   adj_rows  = (const int*)  d_in[1];
    const int*   adj_cols  = (const int*)  d_in[2];
    const float* adj_vals  = (const float*)d_in[3];
    const int*   idxes_seq = (const int*)  d_in[4];
    const int*   idxes_res = (const int*)  d_in[5];
    const float* W         = (const float*)d_in[6];
    const float* b         = (const float*)d_in[7];
    const float* gamma     = (const float*)d_in[8];
    const float* beta      = (const float*)d_in[9];
    float* out = (float*)d_out;

    __half* h = nullptr; __half* s1 = nullptr; __half* s2 = nullptr;
    cudaGetSymbolAddress((void**)&h,  g_h);
    cudaGetSymbolAddress((void**)&s1, g_s1);
    cudaGetSymbolAddress((void**)&s2, g_s2);

    // CSR counts must be zero before the fused rank pass
    zero_cnt_kernel<<<296, 256>>>();
    // fused: tensor-core GEMM (blocks 0..390) + edge rank pass (rest)
    fused_gemm_rank_kernel<<<GEMM_BLOCKS + RANK_BLOCKS, 256>>>(x, W, b, h, adj_rows);
    // rowptr = exclusive-scan(cnt)
    scan1_kernel<<<N_ADJ * NBLK, 512>>>();
    scan2_kernel<<<N_ADJ, 32>>>();
    scan3_kernel<<<296, 256>>>();
    // place entries in CSR order
    place_kernel<<<1184, 256>>>(adj_rows, adj_cols, adj_vals);

    // graph-conv steps (16 lanes per row)
    const int sgrid = (N_NODES * 16 + 255) / 256;
    spmm_h_kernel<<<sgrid, 256>>>(1, idxes_seq + 0, h, nullptr, nullptr, s1);
    spmm_h_kernel<<<sgrid, 256>>>(2, idxes_seq + 1, s1, idxes_res + 0, h, s2);
    spmm_ln_kernel<<<sgrid, 256>>>(idxes_seq + 2, s2, idxes_res + 1, h,
                                   idxes_res + 2, s1, out, gamma, beta);
}

// round 6
// speedup vs baseline: 2.8813x; 1.1113x over previous
#include <cuda_runtime.h>
#include <cuda_fp16.h>
#include <cstdint>

#define N_NODES 50000
#define N_ADJ   6
#define NNZ_C   800000
#define KH      256   // n_hid_prev
#define NH      128   // n_hid
#define LN_EPS  1e-5f
#define NBLK    98    // ceil(50000/512) scan blocks per matrix
#define ABLK    196   // ceil(50000/256) apply blocks per matrix

#define GEMM_BLOCKS ((N_NODES + 127) / 128)   // 391
#define RANK_BLOCKS 1184

// ---------------- scratch (static device globals; no runtime alloc) ----------
__device__ __half g_h [N_NODES * NH];           // states[0] (fp16)
__device__ __half g_s1[N_NODES * NH];           // states[1] (fp16)
__device__ __half g_s2[N_NODES * NH];           // states[2] (fp16)
__device__ int    g_used[N_ADJ];                // 1 if matrix appears in seq/res
__device__ int    g_cnt[N_ADJ * N_NODES];       // per-row counts (atomic ranks)
__device__ int    g_rowptr[N_ADJ * (N_NODES + 1)];
__device__ int    g_bsum[N_ADJ * NBLK];
__device__ int    g_rank[(size_t)N_ADJ * NNZ_C];   // per-edge within-row rank
__device__ int2   g_ent[(size_t)N_ADJ * NNZ_C];    // (col, fp32 val), CSR order

// =============================================================================
// zero counts + compute used-matrix mask
// =============================================================================
__global__ __launch_bounds__(256)
void zero_cnt_kernel(const int* __restrict__ idxes_seq, const int* __restrict__ idxes_res) {
    if (blockIdx.x == 0 && threadIdx.x == 0) {
        int u[N_ADJ];
#pragma unroll
        for (int i = 0; i < N_ADJ; i++) u[i] = 0;
#pragma unroll
        for (int k = 0; k < 3; k++) {
            u[__ldg(idxes_seq + k)] = 1;
            u[__ldg(idxes_res + k)] = 1;
        }
#pragma unroll
        for (int i = 0; i < N_ADJ; i++) g_used[i] = u[i];
    }
    int stride = gridDim.x * blockDim.x;
    for (int i = blockIdx.x * blockDim.x + threadIdx.x; i < N_ADJ * N_NODES; i += stride)
        g_cnt[i] = 0;
}

// =============================================================================
// Fused kernel: blocks [0, GEMM_BLOCKS) do HMMA GEMM; the rest do the rank pass.
// =============================================================================
__device__ __forceinline__ uint32_t smem_u32(const void* p) {
    return (uint32_t)__cvta_generic_to_shared(p);
}

__global__ __launch_bounds__(256)
void fused_gemm_rank_kernel(const float* __restrict__ X, const float* __restrict__ W,
                            const float* __restrict__ bias, __half* __restrict__ H,
                            const int* __restrict__ rows_all) {
    if (blockIdx.x >= GEMM_BLOCKS) {
        // ---------- rank pass: cnt[m][r]++ returning rank, used matrices only
        const int stride = RANK_BLOCKS * 256;
        const int t0 = (blockIdx.x - GEMM_BLOCKS) * 256 + threadIdx.x;
#pragma unroll 1
        for (int m = 0; m < N_ADJ; m++) {
            if (!g_used[m]) continue;
            const int* rows = rows_all + (size_t)m * NNZ_C;
            int* cnt = g_cnt + m * N_NODES;
            int* rnk = g_rank + (size_t)m * NNZ_C;
#pragma unroll 1
            for (int e = t0; e < NNZ_C; e += stride) {
                int r = __ldg(rows + e);
                rnk[e] = atomicAdd(cnt + r, 1);
            }
        }
        return;
    }

    // ---------------- GEMM: H = X[50000,256] @ W[256,128] + b  (fp16 HMMA) ---
    __shared__ __half As[128][40];   // [m][k], pad->conflict-free ldmatrix
    __shared__ __half Bs[32][136];   // [k][n], pad 8

    const int m0   = blockIdx.x * 128;
    const int tid  = threadIdx.x;
    const int wid  = tid >> 5;
    const int lane = tid & 31;
    const int wm   = wid >> 1;          // 0..3 -> rows wm*32
    const int wn   = wid & 1;           // 0..1 -> cols wn*64
    const int grp  = lane >> 3;

    float acc[2][8][4];
#pragma unroll
    for (int a = 0; a < 2; a++)
#pragma unroll
        for (int b = 0; b < 8; b++)
#pragma unroll
            for (int c = 0; c < 4; c++) acc[a][b][c] = 0.f;

    for (int k0 = 0; k0 < KH; k0 += 32) {
#pragma unroll
        for (int i = 0; i < 4; i++) {
            int idx = tid + i * 256;
            int row = idx >> 3;
            int kq  = (idx & 7) * 4;
            float4 v = make_float4(0.f, 0.f, 0.f, 0.f);
            if (m0 + row < N_NODES)
                v = *(const float4*)(X + (size_t)(m0 + row) * KH + k0 + kq);
            *(__half2*)&As[row][kq]     = __floats2half2_rn(v.x, v.y);
            *(__half2*)&As[row][kq + 2] = __floats2half2_rn(v.z, v.w);
        }
#pragma unroll
        for (int i = 0; i < 4; i++) {
            int idx = tid + i * 256;
            int kk  = idx >> 5;
            int nq  = (idx & 31) * 4;
            float4 v = *(const float4*)(W + (size_t)(k0 + kk) * NH + nq);
            *(__half2*)&Bs[kk][nq]     = __floats2half2_rn(v.x, v.y);
            *(__half2*)&Bs[kk][nq + 2] = __floats2half2_rn(v.z, v.w);
        }
        __syncthreads();

#pragma unroll
        for (int ks = 0; ks < 32; ks += 16) {
            uint32_t afr[2][4];
#pragma unroll
            for (int mt = 0; mt < 2; mt++) {
                int arow = wm * 32 + mt * 16 + (lane & 7) + ((grp & 1) << 3);
                int acol = ks + ((grp >> 1) << 3);
                uint32_t addr = smem_u32(&As[arow][acol]);
                asm volatile("ldmatrix.sync.aligned.m8n8.x4.shared.b16 {%0,%1,%2,%3}, [%4];"
                             : "=r"(afr[mt][0]), "=r"(afr[mt][1]),
                               "=r"(afr[mt][2]), "=r"(afr[mt][3]) : "r"(addr));
            }
            uint32_t bfr[8][2];
#pragma unroll
            for (int p = 0; p < 4; p++) {
                int brow = ks + ((grp & 1) << 3) + (lane & 7);
                int bcol = wn * 64 + p * 16 + ((grp >> 1) << 3);
                uint32_t addr = smem_u32(&Bs[brow][bcol]);
                asm volatile("ldmatrix.sync.aligned.m8n8.x4.trans.shared.b16 {%0,%1,%2,%3}, [%4];"
                             : "=r"(bfr[2 * p][0]), "=r"(bfr[2 * p][1]),
                               "=r"(bfr[2 * p + 1][0]), "=r"(bfr[2 * p + 1][1]) : "r"(addr));
            }
#pragma unroll
            for (int mt = 0; mt < 2; mt++)
#pragma unroll
                for (int nt = 0; nt < 8; nt++) {
                    asm volatile(
                        "mma.sync.aligned.m16n8k16.row.col.f32.f16.f16.f32 "
                        "{%0,%1,%2,%3}, {%4,%5,%6,%7}, {%8,%9}, {%0,%1,%2,%3};"
                        : "+f"(acc[mt][nt][0]), "+f"(acc[mt][nt][1]),
                          "+f"(acc[mt][nt][2]), "+f"(acc[mt][nt][3])
                        : "r"(afr[mt][0]), "r"(afr[mt][1]),
                          "r"(afr[mt][2]), "r"(afr[mt][3]),
                          "r"(bfr[nt][0]), "r"(bfr[nt][1]));
                }
        }
        __syncthreads();
    }

#pragma unroll
    for (int mt = 0; mt < 2; mt++) {
        int row0 = m0 + wm * 32 + mt * 16 + (lane >> 2);
#pragma unroll
        for (int nt = 0; nt < 8; nt++) {
            int col = wn * 64 + nt * 8 + (lane & 3) * 2;
            float b0 = __ldg(bias + col), b1 = __ldg(bias + col + 1);
            if (row0 < N_NODES) {
                __half2 o = __floats2half2_rn(acc[mt][nt][0] + b0, acc[mt][nt][1] + b1);
                *(__half2*)(H + (size_t)row0 * NH + col) = o;
            }
            if (row0 + 8 < N_NODES) {
                __half2 o = __floats2half2_rn(acc[mt][nt][2] + b0, acc[mt][nt][3] + b1);
                *(__half2*)(H + (size_t)(row0 + 8) * NH + col) = o;
            }
        }
    }
}

// ---------------- CSR scans ---------------------------------------------------
__global__ __launch_bounds__(512)
void scan1_kernel() {
    const int m   = blockIdx.x / NBLK;
    if (!g_used[m]) return;
    const int blk = blockIdx.x % NBLK;
    const int tid = threadIdx.x;
    const int i   = blk * 512 + tid;

    int v = (i < N_NODES) ? g_cnt[m * N_NODES + i] : 0;
    int x = v;
    const int lane = tid & 31;
#pragma unroll
    for (int o = 1; o < 32; o <<= 1) {
        int n = __shfl_up_sync(0xffffffffu, x, o);
        if (lane >= o) x += n;
    }
    __shared__ int ws[16];
    if (lane == 31) ws[tid >> 5] = x;
    __syncthreads();
    if (tid < 16) {
        int y = ws[tid];
#pragma unroll
        for (int o = 1; o < 16; o <<= 1) {
            int n = __shfl_up_sync(0x0000ffffu, y, o);
            if (tid >= o) y += n;
        }
        ws[tid] = y;
    }
    __syncthreads();
    int w = tid >> 5;
    int off = (w > 0) ? ws[w - 1] : 0;
    int incl = x + off;
    if (i < N_NODES)
        g_rowptr[m * (N_NODES + 1) + i] = incl - v;
    if (tid == 511)
        g_bsum[blockIdx.x] = incl;
}

// fused scan2+scan3: each block re-derives the 98-entry block-sum prefix in smem
__global__ __launch_bounds__(256)
void scan23_kernel() {
    const int m   = blockIdx.x / ABLK;
    if (!g_used[m]) return;
    const int blk = blockIdx.x % ABLK;
    const int tid = threadIdx.x;

    __shared__ int pre[NBLK];
    if (tid < 32) {
        int v[4]; int s = 0;
#pragma unroll
        for (int k = 0; k < 4; k++) {
            int i = tid * 4 + k;
            v[k] = (i < NBLK) ? g_bsum[m * NBLK + i] : 0;
            s += v[k];
        }
        int x = s;
#pragma unroll
        for (int o = 1; o < 32; o <<= 1) {
            int n = __shfl_up_sync(0xffffffffu, x, o);
            if (tid >= o) x += n;
        }
        int excl = x - s;
#pragma unroll
        for (int k = 0; k < 4; k++) {
            int i = tid * 4 + k;
            if (i < NBLK) pre[i] = excl;
            excl += v[k];
        }
    }
    __syncthreads();

    int r = blk * 256 + tid;
    if (r < N_NODES)
        g_rowptr[m * (N_NODES + 1) + r] += pre[r >> 9];
    if (blk == 0 && tid == 0)
        g_rowptr[m * (N_NODES + 1) + N_NODES] = NNZ_C;
}

__global__ __launch_bounds__(256)
void place_kernel(const int* __restrict__ rows_all, const int* __restrict__ cols_all,
                  const float* __restrict__ vals_all) {
    const int stride = gridDim.x * blockDim.x;
    const int t0 = blockIdx.x * blockDim.x + threadIdx.x;
#pragma unroll 1
    for (int m = 0; m < N_ADJ; m++) {
        if (!g_used[m]) continue;
        const int*   rows = rows_all + (size_t)m * NNZ_C;
        const int*   cols = cols_all + (size_t)m * NNZ_C;
        const float* vals = vals_all + (size_t)m * NNZ_C;
        const int*   rnk  = g_rank + (size_t)m * NNZ_C;
        const int*   rp   = g_rowptr + m * (N_NODES + 1);
        int2*        ent  = g_ent + (size_t)m * NNZ_C;
#pragma unroll 1
        for (int e = t0; e < NNZ_C; e += stride) {
            int r = __ldg(rows + e);
            int c = __ldg(cols + e);
            float v = __ldg(vals + e);
            int pos = __ldg(rp + r) + __ldg(rnk + e);
            ent[pos] = make_int2(c, __float_as_int(v));
        }
    }
}

// ---------------- SpMM: 16 lanes per row, 4-deep entry prefetch ---------------
__device__ __forceinline__ void fma8(float* acc, float v, uint4 raw) {
    const __half2* h = (const __half2*)&raw;
#pragma unroll
    for (int q = 0; q < 4; q++) {
        float2 f = __half22float2(h[q]);
        acc[2 * q]     += v * f.x;
        acc[2 * q + 1] += v * f.y;
    }
}

__device__ __forceinline__ void row_accum16(int a, int row, int lane16,
                                            const __half* __restrict__ src, float* acc) {
    const int2* ent = g_ent + (size_t)a * NNZ_C;
    const int base = a * (N_NODES + 1);
    int s = __ldg(&g_rowptr[base + row]);
    int e = __ldg(&g_rowptr[base + row + 1]);
    int j = s;
    for (; j + 4 <= e; j += 4) {
        int2 c0 = __ldg(ent + j);
        int2 c1 = __ldg(ent + j + 1);
        int2 c2 = __ldg(ent + j + 2);
        int2 c3 = __ldg(ent + j + 3);
        uint4 r0 = __ldg((const uint4*)(src + (size_t)c0.x * NH) + lane16);
        uint4 r1 = __ldg((const uint4*)(src + (size_t)c1.x * NH) + lane16);
        uint4 r2 = __ldg((const uint4*)(src + (size_t)c2.x * NH) + lane16);
        uint4 r3 = __ldg((const uint4*)(src + (size_t)c3.x * NH) + lane16);
        fma8(acc, __int_as_float(c0.y), r0);
        fma8(acc, __int_as_float(c1.y), r1);
        fma8(acc, __int_as_float(c2.y), r2);
        fma8(acc, __int_as_float(c3.y), r3);
    }
    for (; j < e; j++) {
        int2 cv = __ldg(ent + j);
        uint4 rv = __ldg((const uint4*)(src + (size_t)cv.x * NH) + lane16);
        fma8(acc, __int_as_float(cv.y), rv);
    }
}

// steps 0/1: dst (fp16) = sum of 1..2 SpMMs
__global__ __launch_bounds__(256)
void spmm_h_kernel(int nmat,
                   const int* __restrict__ ia0, const __half* __restrict__ src0,
                   const int* __restrict__ ia1, const __half* __restrict__ src1,
                   __half* __restrict__ dst) {
    const int row = (blockIdx.x * blockDim.x + threadIdx.x) >> 4;
    if (row >= N_NODES) return;
    const int lane16 = threadIdx.x & 15;

    float acc[8];
#pragma unroll
    for (int q = 0; q < 8; q++) acc[q] = 0.f;
    row_accum16(__ldg(ia0), row, lane16, src0, acc);
    if (nmat > 1) row_accum16(__ldg(ia1), row, lane16, src1, acc);

    __half2 p[4];
#pragma unroll
    for (int q = 0; q < 4; q++) p[q] = __floats2half2_rn(acc[2 * q], acc[2 * q + 1]);
    uint4 o;
    o.x = *(unsigned*)&p[0]; o.y = *(unsigned*)&p[1];
    o.z = *(unsigned*)&p[2]; o.w = *(unsigned*)&p[3];
    *((uint4*)(dst + (size_t)row * NH) + lane16) = o;
}

// step 2: out (fp32) = LN+GELU( sum of 3 SpMMs )
__global__ __launch_bounds__(256)
void spmm_ln_kernel(const int* __restrict__ ia0, const __half* __restrict__ src0,
                    const int* __restrict__ ia1, const __half* __restrict__ src1,
                    const int* __restrict__ ia2, const __half* __restrict__ src2,
                    float* __restrict__ dst,
                    const float* __restrict__ gamma, const float* __restrict__ beta) {
    const int row = (blockIdx.x * blockDim.x + threadIdx.x) >> 4;
    if (row >= N_NODES) return;
    const int lane16 = threadIdx.x & 15;

    float acc[8];
#pragma unroll
    for (int q = 0; q < 8; q++) acc[q] = 0.f;
    row_accum16(__ldg(ia0), row, lane16, src0, acc);
    row_accum16(__ldg(ia1), row, lane16, src1, acc);
    row_accum16(__ldg(ia2), row, lane16, src2, acc);

    float s = 0.f, s2 = 0.f;
#pragma unroll
    for (int q = 0; q < 8; q++) { s += acc[q]; s2 += acc[q] * acc[q]; }
#pragma unroll
    for (int o = 8; o; o >>= 1) {
        s  += __shfl_xor_sync(0xffffffffu, s,  o, 16);
        s2 += __shfl_xor_sync(0xffffffffu, s2, o, 16);
    }
    float mu  = s * (1.f / NH);
    float var = s2 * (1.f / NH) - mu * mu;
    float inv = rsqrtf(var + LN_EPS);

    float4 g0 = *(const float4*)(gamma + lane16 * 8);
    float4 g1 = *(const float4*)(gamma + lane16 * 8 + 4);
    float4 b0 = *(const float4*)(beta  + lane16 * 8);
    float4 b1 = *(const float4*)(beta  + lane16 * 8 + 4);
    const float gv[8] = {g0.x, g0.y, g0.z, g0.w, g1.x, g1.y, g1.z, g1.w};
    const float bv[8] = {b0.x, b0.y, b0.z, b0.w, b1.x, b1.y, b1.z, b1.w};

    const float kk = 0.70710678118654752f;
    float o8[8];
#pragma unroll
    for (int q = 0; q < 8; q++) {
        float y = (acc[q] - mu) * inv * gv[q] + bv[q];
        o8[q] = 0.5f * y * (1.f + erff(y * kk));
    }
    float* dp = dst + (size_t)row * NH + lane16 * 8;
    *(float4*)dp       = make_float4(o8[0], o8[1], o8[2], o8[3]);
    *(float4*)(dp + 4) = make_float4(o8[4], o8[5], o8[6], o8[7]);
}

// -----------------------------------------------------------------------------
extern "C" void kernel_launch(void* const* d_in, const int* in_sizes, int n_in,
                              void* d_out, int out_size) {
    const float* x         = (const float*)d_in[0];
    const int*   adj_rows  = (const int*)  d_in[1];
    const int*   adj_cols  = (const int*)  d_in[2];
    const float* adj_vals  = (const float*)d_in[3];
    const int*   idxes_seq = (const int*)  d_in[4];
    const int*   idxes_res = (const int*)  d_in[5];
    const float* W         = (const float*)d_in[6];
    const float* b         = (const float*)d_in[7];
    const float* gamma     = (const float*)d_in[8];
    const float* beta      = (const float*)d_in[9];
    float* out = (float*)d_out;

    __half* h = nullptr; __half* s1 = nullptr; __half* s2 = nullptr;
    cudaGetSymbolAddress((void**)&h,  g_h);
    cudaGetSymbolAddress((void**)&s1, g_s1);
    cudaGetSymbolAddress((void**)&s2, g_s2);

    // zero counts + compute used-matrix mask
    zero_cnt_kernel<<<296, 256>>>(idxes_seq, idxes_res);
    // fused: tensor-core GEMM (blocks 0..390) + edge rank pass (rest, mask-gated)
    fused_gemm_rank_kernel<<<GEMM_BLOCKS + RANK_BLOCKS, 256>>>(x, W, b, h, adj_rows);
    // rowptr = exclusive-scan(cnt), used matrices only
    scan1_kernel<<<N_ADJ * NBLK, 512>>>();
    scan23_kernel<<<N_ADJ * ABLK, 256>>>();
    // place entries in CSR order, used matrices only
    place_kernel<<<1184, 256>>>(adj_rows, adj_cols, adj_vals);

    // graph-conv steps (16 lanes per row)
    const int sgrid = (N_NODES * 16 + 255) / 256;
    spmm_h_kernel<<<sgrid, 256>>>(1, idxes_seq + 0, h, nullptr, nullptr, s1);
    spmm_h_kernel<<<sgrid, 256>>>(2, idxes_seq + 1, s1, idxes_res + 0, h, s2);
    spmm_ln_kernel<<<sgrid, 256>>>(idxes_seq + 2, s2, idxes_res + 1, h,
                                   idxes_res + 2, s1, out, gamma, beta);
}

// round 9
// speedup vs baseline: 3.1205x; 1.0830x over previous
#include <cuda_runtime.h>
#include <cuda_fp16.h>
#include <cstdint>

#define N_NODES 50000
#define N_ADJ   6
#define NNZ_C   800000
#define KH      256   // n_hid_prev
#define NH      128   // n_hid
#define LN_EPS  1e-5f
#define NBLK    98    // ceil(50000/512) scan blocks per matrix
#define ABLK    196   // ceil(50000/256) apply blocks per matrix

#define GEMM_BLOCKS  ((N_NODES + 127) / 128)   // 391
#define RANK_BLOCKS  1184
#define PLACE_BLOCKS 592
#define SPMM_BLOCKS  ((N_NODES * 16 + 255) / 256)   // 3125

// ---------------- scratch (static device globals; zero-initialized) ----------
__device__ __half g_h [N_NODES * NH];           // states[0] (fp16)
__device__ __half g_s1[N_NODES * NH];           // states[1] (fp16)
__device__ __half g_s2[N_NODES * NH];           // states[2] (fp16)
__device__ int    g_cnt[N_ADJ * N_NODES];       // per-row counts (re-zeroed by scan1)
__device__ int    g_cur[N_ADJ * N_NODES];       // placement cursors
__device__ int    g_rowptr[N_ADJ * (N_NODES + 1)];
__device__ int    g_bsum[N_ADJ * NBLK];
__device__ int2   g_ent[(size_t)N_ADJ * NNZ_C]; // (col, fp32 val), CSR order

// used-matrix bitmask from the device-resident index arrays
__device__ __forceinline__ int used_mask(const int* __restrict__ seq,
                                         const int* __restrict__ res) {
    int mask = 0;
#pragma unroll
    for (int k = 0; k < 3; k++) {
        mask |= 1 << __ldg(seq + k);
        mask |= 1 << __ldg(res + k);
    }
    return mask;
}

__device__ __forceinline__ uint32_t smem_u32(const void* p) {
    return (uint32_t)__cvta_generic_to_shared(p);
}

// place 4 edges (one int4/float4 quad) using cursor atomics
__device__ __forceinline__ void place_quad(int* __restrict__ cur, int2* __restrict__ ent,
                                           int4 r, int4 c, float4 v) {
    int p0 = atomicAdd(cur + r.x, 1);
    int p1 = atomicAdd(cur + r.y, 1);
    int p2 = atomicAdd(cur + r.z, 1);
    int p3 = atomicAdd(cur + r.w, 1);
    ent[p0] = make_int2(c.x, __float_as_int(v.x));
    ent[p1] = make_int2(c.y, __float_as_int(v.y));
    ent[p2] = make_int2(c.z, __float_as_int(v.z));
    ent[p3] = make_int2(c.w, __float_as_int(v.w));
}

// =============================================================================
// Fused: blocks [0, GEMM_BLOCKS) = HMMA GEMM; rest = count pass (pure RED).
// =============================================================================
__global__ __launch_bounds__(256)
void fused_gemm_count_kernel(const float* __restrict__ X, const float* __restrict__ W,
                             const float* __restrict__ bias, __half* __restrict__ H,
                             const int* __restrict__ rows_all,
                             const int* __restrict__ seq, const int* __restrict__ res) {
    if (blockIdx.x >= GEMM_BLOCKS) {
        const int mask = used_mask(seq, res);
        const int nq = NNZ_C / 4;
        const int stride = RANK_BLOCKS * 256;
        const int t0 = (blockIdx.x - GEMM_BLOCKS) * 256 + threadIdx.x;
#pragma unroll 1
        for (int m = 0; m < N_ADJ; m++) {
            if (!((mask >> m) & 1)) continue;
            const int4* rows4 = (const int4*)(rows_all + (size_t)m * NNZ_C);
            int* cnt = g_cnt + m * N_NODES;
#pragma unroll 1
            for (int q = t0; q < nq; q += stride) {
                int4 r = __ldg(rows4 + q);
                atomicAdd(cnt + r.x, 1);
                atomicAdd(cnt + r.y, 1);
                atomicAdd(cnt + r.z, 1);
                atomicAdd(cnt + r.w, 1);
            }
        }
        return;
    }

    // ---------------- GEMM: H = X[50000,256] @ W[256,128] + b  (fp16 HMMA) ---
    __shared__ __half As[128][40];
    __shared__ __half Bs[32][136];

    const int m0   = blockIdx.x * 128;
    const int tid  = threadIdx.x;
    const int wid  = tid >> 5;
    const int lane = tid & 31;
    const int wm   = wid >> 1;
    const int wn   = wid & 1;
    const int grp  = lane >> 3;

    float acc[2][8][4];
#pragma unroll
    for (int a = 0; a < 2; a++)
#pragma unroll
        for (int b = 0; b < 8; b++)
#pragma unroll
            for (int c = 0; c < 4; c++) acc[a][b][c] = 0.f;

    for (int k0 = 0; k0 < KH; k0 += 32) {
#pragma unroll
        for (int i = 0; i < 4; i++) {
            int idx = tid + i * 256;
            int row = idx >> 3;
            int kq  = (idx & 7) * 4;
            float4 v = make_float4(0.f, 0.f, 0.f, 0.f);
            if (m0 + row < N_NODES)
                v = *(const float4*)(X + (size_t)(m0 + row) * KH + k0 + kq);
            *(__half2*)&As[row][kq]     = __floats2half2_rn(v.x, v.y);
            *(__half2*)&As[row][kq + 2] = __floats2half2_rn(v.z, v.w);
        }
#pragma unroll
        for (int i = 0; i < 4; i++) {
            int idx = tid + i * 256;
            int kk  = idx >> 5;
            int nq2 = (idx & 31) * 4;
            float4 v = *(const float4*)(W + (size_t)(k0 + kk) * NH + nq2);
            *(__half2*)&Bs[kk][nq2]     = __floats2half2_rn(v.x, v.y);
            *(__half2*)&Bs[kk][nq2 + 2] = __floats2half2_rn(v.z, v.w);
        }
        __syncthreads();

#pragma unroll
        for (int ks = 0; ks < 32; ks += 16) {
            uint32_t afr[2][4];
#pragma unroll
            for (int mt = 0; mt < 2; mt++) {
                int arow = wm * 32 + mt * 16 + (lane & 7) + ((grp & 1) << 3);
                int acol = ks + ((grp >> 1) << 3);
                uint32_t addr = smem_u32(&As[arow][acol]);
                asm volatile("ldmatrix.sync.aligned.m8n8.x4.shared.b16 {%0,%1,%2,%3}, [%4];"
                             : "=r"(afr[mt][0]), "=r"(afr[mt][1]),
                               "=r"(afr[mt][2]), "=r"(afr[mt][3]) : "r"(addr));
            }
            uint32_t bfr[8][2];
#pragma unroll
            for (int p = 0; p < 4; p++) {
                int brow = ks + ((grp & 1) << 3) + (lane & 7);
                int bcol = wn * 64 + p * 16 + ((grp >> 1) << 3);
                uint32_t addr = smem_u32(&Bs[brow][bcol]);
                asm volatile("ldmatrix.sync.aligned.m8n8.x4.trans.shared.b16 {%0,%1,%2,%3}, [%4];"
                             : "=r"(bfr[2 * p][0]), "=r"(bfr[2 * p][1]),
                               "=r"(bfr[2 * p + 1][0]), "=r"(bfr[2 * p + 1][1]) : "r"(addr));
            }
#pragma unroll
            for (int mt = 0; mt < 2; mt++)
#pragma unroll
                for (int nt = 0; nt < 8; nt++) {
                    asm volatile(
                        "mma.sync.aligned.m16n8k16.row.col.f32.f16.f16.f32 "
                        "{%0,%1,%2,%3}, {%4,%5,%6,%7}, {%8,%9}, {%0,%1,%2,%3};"
                        : "+f"(acc[mt][nt][0]), "+f"(acc[mt][nt][1]),
                          "+f"(acc[mt][nt][2]), "+f"(acc[mt][nt][3])
                        : "r"(afr[mt][0]), "r"(afr[mt][1]),
                          "r"(afr[mt][2]), "r"(afr[mt][3]),
                          "r"(bfr[nt][0]), "r"(bfr[nt][1]));
                }
        }
        __syncthreads();
    }

#pragma unroll
    for (int mt = 0; mt < 2; mt++) {
        int row0 = m0 + wm * 32 + mt * 16 + (lane >> 2);
#pragma unroll
        for (int nt = 0; nt < 8; nt++) {
            int col = wn * 64 + nt * 8 + (lane & 3) * 2;
            float b0 = __ldg(bias + col), b1 = __ldg(bias + col + 1);
            if (row0 < N_NODES) {
                __half2 o = __floats2half2_rn(acc[mt][nt][0] + b0, acc[mt][nt][1] + b1);
                *(__half2*)(H + (size_t)row0 * NH + col) = o;
            }
            if (row0 + 8 < N_NODES) {
                __half2 o = __floats2half2_rn(acc[mt][nt][2] + b0, acc[mt][nt][3] + b1);
                *(__half2*)(H + (size_t)(row0 + 8) * NH + col) = o;
            }
        }
    }
}

// ---------------- CSR scans ---------------------------------------------------
__global__ __launch_bounds__(512)
void scan1_kernel(const int* __restrict__ seq, const int* __restrict__ res) {
    const int m = blockIdx.x / NBLK;
    if (!((used_mask(seq, res) >> m) & 1)) return;
    const int blk = blockIdx.x % NBLK;
    const int tid = threadIdx.x;
    const int i   = blk * 512 + tid;

    int v = (i < N_NODES) ? g_cnt[m * N_NODES + i] : 0;
    if (i < N_NODES) g_cnt[m * N_NODES + i] = 0;   // reset for next replay
    int x = v;
    const int lane = tid & 31;
#pragma unroll
    for (int o = 1; o < 32; o <<= 1) {
        int n = __shfl_up_sync(0xffffffffu, x, o);
        if (lane >= o) x += n;
    }
    __shared__ int ws[16];
    if (lane == 31) ws[tid >> 5] = x;
    __syncthreads();
    if (tid < 16) {
        int y = ws[tid];
#pragma unroll
        for (int o = 1; o < 16; o <<= 1) {
            int n = __shfl_up_sync(0x0000ffffu, y, o);
            if (tid >= o) y += n;
        }
        ws[tid] = y;
    }
    __syncthreads();
    int w = tid >> 5;
    int off = (w > 0) ? ws[w - 1] : 0;
    int incl = x + off;
    if (i < N_NODES)
        g_rowptr[m * (N_NODES + 1) + i] = incl - v;
    if (tid == 511)
        g_bsum[blockIdx.x] = incl;
}

// fused scan2+scan3: finalize rowptr, seed cursors
__global__ __launch_bounds__(256)
void scan23_kernel(const int* __restrict__ seq, const int* __restrict__ res) {
    const int m = blockIdx.x / ABLK;
    if (!((used_mask(seq, res) >> m) & 1)) return;
    const int blk = blockIdx.x % ABLK;
    const int tid = threadIdx.x;

    __shared__ int pre[NBLK];
    if (tid < 32) {
        int v[4]; int s = 0;
#pragma unroll
        for (int k = 0; k < 4; k++) {
            int i = tid * 4 + k;
            v[k] = (i < NBLK) ? g_bsum[m * NBLK + i] : 0;
            s += v[k];
        }
        int x = s;
#pragma unroll
        for (int o = 1; o < 32; o <<= 1) {
            int n = __shfl_up_sync(0xffffffffu, x, o);
            if (tid >= o) x += n;
        }
        int excl = x - s;
#pragma unroll
        for (int k = 0; k < 4; k++) {
            int i = tid * 4 + k;
            if (i < NBLK) pre[i] = excl;
            excl += v[k];
        }
    }
    __syncthreads();

    int r = blk * 256 + tid;
    if (r < N_NODES) {
        int val = g_rowptr[m * (N_NODES + 1) + r] + pre[r >> 9];
        g_rowptr[m * (N_NODES + 1) + r] = val;
        g_cur[m * N_NODES + r] = val;
    }
    if (blk == 0 && tid == 0)
        g_rowptr[m * (N_NODES + 1) + N_NODES] = NNZ_C;
}

// place ONLY seq0's matrix (unblocks SpMM step 0)
__global__ __launch_bounds__(256)
void place_first_kernel(const int* __restrict__ rows_all, const int* __restrict__ cols_all,
                        const float* __restrict__ vals_all, const int* __restrict__ seq) {
    const int m = __ldg(seq + 0);
    const int4*   rows4 = (const int4*)  (rows_all + (size_t)m * NNZ_C);
    const int4*   cols4 = (const int4*)  (cols_all + (size_t)m * NNZ_C);
    const float4* vals4 = (const float4*)(vals_all + (size_t)m * NNZ_C);
    int*  cur = g_cur + m * N_NODES;
    int2* ent = g_ent + (size_t)m * NNZ_C;

    const int nq = NNZ_C / 4;
    const int stride = gridDim.x * blockDim.x;
    for (int q = blockIdx.x * blockDim.x + threadIdx.x; q < nq; q += stride)
        place_quad(cur, ent, __ldg(rows4 + q), __ldg(cols4 + q), __ldg(vals4 + q));
}

// ---------------- SpMM primitives --------------------------------------------
__device__ __forceinline__ void fma8(float* acc, float v, uint4 raw) {
    const __half2* h = (const __half2*)&raw;
#pragma unroll
    for (int q = 0; q < 4; q++) {
        float2 f = __half22float2(h[q]);
        acc[2 * q]     += v * f.x;
        acc[2 * q + 1] += v * f.y;
    }
}

__device__ __forceinline__ void row_accum16(int a, int row, int lane16,
                                            const __half* __restrict__ src, float* acc) {
    const int2* ent = g_ent + (size_t)a * NNZ_C;
    const int base = a * (N_NODES + 1);
    int s = __ldg(&g_rowptr[base + row]);
    int e = __ldg(&g_rowptr[base + row + 1]);
    int j = s;
    for (; j + 4 <= e; j += 4) {
        int2 c0 = __ldg(ent + j);
        int2 c1 = __ldg(ent + j + 1);
        int2 c2 = __ldg(ent + j + 2);
        int2 c3 = __ldg(ent + j + 3);
        uint4 r0 = __ldg((const uint4*)(src + (size_t)c0.x * NH) + lane16);
        uint4 r1 = __ldg((const uint4*)(src + (size_t)c1.x * NH) + lane16);
        uint4 r2 = __ldg((const uint4*)(src + (size_t)c2.x * NH) + lane16);
        uint4 r3 = __ldg((const uint4*)(src + (size_t)c3.x * NH) + lane16);
        fma8(acc, __int_as_float(c0.y), r0);
        fma8(acc, __int_as_float(c1.y), r1);
        fma8(acc, __int_as_float(c2.y), r2);
        fma8(acc, __int_as_float(c3.y), r3);
    }
    for (; j < e; j++) {
        int2 cv = __ldg(ent + j);
        uint4 rv = __ldg((const uint4*)(src + (size_t)cv.x * NH) + lane16);
        fma8(acc, __int_as_float(cv.y), rv);
    }
}

__device__ __forceinline__ void store_row_h(__half* __restrict__ dst, int row,
                                            int lane16, const float* acc) {
    __half2 p[4];
#pragma unroll
    for (int q = 0; q < 4; q++) p[q] = __floats2half2_rn(acc[2 * q], acc[2 * q + 1]);
    uint4 o;
    o.x = *(unsigned*)&p[0]; o.y = *(unsigned*)&p[1];
    o.z = *(unsigned*)&p[2]; o.w = *(unsigned*)&p[3];
    *((uint4*)(dst + (size_t)row * NH) + lane16) = o;
}

// =============================================================================
// Fused: blocks [0, PLACE_BLOCKS) place remaining used matrices;
//        blocks [PLACE_BLOCKS, +SPMM_BLOCKS) run SpMM step 0 (s1 = A[seq0] @ h)
// NOTE: the SpMM half depends ONLY on seq0's entries, which were fully placed
// by place_first_kernel in the PREVIOUS launch — no intra-kernel dependency.
// =============================================================================
__global__ __launch_bounds__(256)
void fused_place_spmm0_kernel(const int* __restrict__ rows_all, const int* __restrict__ cols_all,
                              const float* __restrict__ vals_all,
                              const int* __restrict__ seq, const int* __restrict__ res,
                              const __half* __restrict__ h, __half* __restrict__ s1) {
    if (blockIdx.x < PLACE_BLOCKS) {
        const int mask = used_mask(seq, res);
        const int m0q = __ldg(seq + 0);
        const int nq = NNZ_C / 4;
        const int stride = PLACE_BLOCKS * 256;
        const int t0 = blockIdx.x * 256 + threadIdx.x;
#pragma unroll 1
        for (int m = 0; m < N_ADJ; m++) {
            if (m == m0q || !((mask >> m) & 1)) continue;
            const int4*   rows4 = (const int4*)  (rows_all + (size_t)m * NNZ_C);
            const int4*   cols4 = (const int4*)  (cols_all + (size_t)m * NNZ_C);
            const float4* vals4 = (const float4*)(vals_all + (size_t)m * NNZ_C);
            int*  cur = g_cur + m * N_NODES;
            int2* ent = g_ent + (size_t)m * NNZ_C;
#pragma unroll 1
            for (int q = t0; q < nq; q += stride)
                place_quad(cur, ent, __ldg(rows4 + q), __ldg(cols4 + q), __ldg(vals4 + q));
        }
        return;
    }

    const int bid = blockIdx.x - PLACE_BLOCKS;
    const int row = (bid * 256 + threadIdx.x) >> 4;
    if (row >= N_NODES) return;
    const int lane16 = threadIdx.x & 15;

    float acc[8];
#pragma unroll
    for (int q = 0; q < 8; q++) acc[q] = 0.f;
    row_accum16(__ldg(seq + 0), row, lane16, h, acc);
    store_row_h(s1, row, lane16, acc);
}

// step 1: s2 (fp16) = A[seq1] @ s1 + A[res0] @ h
__global__ __launch_bounds__(256)
void spmm_step1_kernel(const int* __restrict__ seq, const int* __restrict__ res,
                       const __half* __restrict__ s1, const __half* __restrict__ h,
                       __half* __restrict__ s2) {
    const int row = (blockIdx.x * blockDim.x + threadIdx.x) >> 4;
    if (row >= N_NODES) return;
    const int lane16 = threadIdx.x & 15;

    float acc[8];
#pragma unroll
    for (int q = 0; q < 8; q++) acc[q] = 0.f;
    row_accum16(__ldg(seq + 1), row, lane16, s1, acc);
    row_accum16(__ldg(res + 0), row, lane16, h,  acc);
    store_row_h(s2, row, lane16, acc);
}

// step 2: out (fp32) = LN+GELU( A[seq2]@s2 + A[res1]@h + A[res2]@s1 )
__global__ __launch_bounds__(256)
void spmm_ln_kernel(const int* __restrict__ seq, const int* __restrict__ res,
                    const __half* __restrict__ s2, const __half* __restrict__ h,
                    const __half* __restrict__ s1, float* __restrict__ dst,
                    const float* __restrict__ gamma, const float* __restrict__ beta) {
    const int row = (blockIdx.x * blockDim.x + threadIdx.x) >> 4;
    if (row >= N_NODES) return;
    const int lane16 = threadIdx.x & 15;

    float acc[8];
#pragma unroll
    for (int q = 0; q < 8; q++) acc[q] = 0.f;
    row_accum16(__ldg(seq + 2), row, lane16, s2, acc);
    row_accum16(__ldg(res + 1), row, lane16, h,  acc);
    row_accum16(__ldg(res + 2), row, lane16, s1, acc);

    float s = 0.f, s2v = 0.f;
#pragma unroll
    for (int q = 0; q < 8; q++) { s += acc[q]; s2v += acc[q] * acc[q]; }
#pragma unroll
    for (int o = 8; o; o >>= 1) {
        s   += __shfl_xor_sync(0xffffffffu, s,   o, 16);
        s2v += __shfl_xor_sync(0xffffffffu, s2v, o, 16);
    }
    float mu  = s * (1.f / NH);
    float var = s2v * (1.f / NH) - mu * mu;
    float inv = rsqrtf(var + LN_EPS);

    float4 g0 = *(const float4*)(gamma + lane16 * 8);
    float4 g1 = *(const float4*)(gamma + lane16 * 8 + 4);
    float4 b0 = *(const float4*)(beta  + lane16 * 8);
    float4 b1 = *(const float4*)(beta  + lane16 * 8 + 4);
    const float gv[8] = {g0.x, g0.y, g0.z, g0.w, g1.x, g1.y, g1.z, g1.w};
    const float bv[8] = {b0.x, b0.y, b0.z, b0.w, b1.x, b1.y, b1.z, b1.w};

    const float kk = 0.70710678118654752f;
    float o8[8];
#pragma unroll
    for (int q = 0; q < 8; q++) {
        float y = (acc[q] - mu) * inv * gv[q] + bv[q];
        o8[q] = 0.5f * y * (1.f + erff(y * kk));
    }
    float* dp = dst + (size_t)row * NH + lane16 * 8;
    *(float4*)dp       = make_float4(o8[0], o8[1], o8[2], o8[3]);
    *(float4*)(dp + 4) = make_float4(o8[4], o8[5], o8[6], o8[7]);
}

// -----------------------------------------------------------------------------
extern "C" void kernel_launch(void* const* d_in, const int* in_sizes, int n_in,
                              void* d_out, int out_size) {
    const float* x         = (const float*)d_in[0];
    const int*   adj_rows  = (const int*)  d_in[1];
    const int*   adj_cols  = (const int*)  d_in[2];
    const float* adj_vals  = (const float*)d_in[3];
    const int*   idxes_seq = (const int*)  d_in[4];
    const int*   idxes_res = (const int*)  d_in[5];
    const float* W         = (const float*)d_in[6];
    const float* b         = (const float*)d_in[7];
    const float* gamma     = (const float*)d_in[8];
    const float* beta      = (const float*)d_in[9];
    float* out = (float*)d_out;

    __half* h = nullptr; __half* s1 = nullptr; __half* s2 = nullptr;
    cudaGetSymbolAddress((void**)&h,  g_h);
    cudaGetSymbolAddress((void**)&s1, g_s1);
    cudaGetSymbolAddress((void**)&s2, g_s2);

    // 1. HMMA GEMM (h = xW+b) overlapped with edge count pass (RED only)
    fused_gemm_count_kernel<<<GEMM_BLOCKS + RANK_BLOCKS, 256>>>(
        x, W, b, h, adj_rows, idxes_seq, idxes_res);
    // 2-3. rowptr = exclusive-scan(cnt); cnt re-zeroed; cursors seeded
    scan1_kernel<<<N_ADJ * NBLK, 512>>>(idxes_seq, idxes_res);
    scan23_kernel<<<N_ADJ * ABLK, 256>>>(idxes_seq, idxes_res);
    // 4. place seq0's matrix only
    place_first_kernel<<<1024, 256>>>(adj_rows, adj_cols, adj_vals, idxes_seq);
    // 5. place remaining matrices overlapped with SpMM step 0
    fused_place_spmm0_kernel<<<PLACE_BLOCKS + SPMM_BLOCKS, 256>>>(
        adj_rows, adj_cols, adj_vals, idxes_seq, idxes_res, h, s1);
    // 6-7. remaining steps
    spmm_step1_kernel<<<SPMM_BLOCKS, 256>>>(idxes_seq, idxes_res, s1, h, s2);
    spmm_ln_kernel<<<SPMM_BLOCKS, 256>>>(idxes_seq, idxes_res, s2, h, s1,
                                         out, gamma, beta);
}